// round 11
// baseline (speedup 1.0000x reference)
#include <cuda_runtime.h>
#include <cuda_fp16.h>
#include <cstdint>

#define NFACT 100000
#define NCOMP 10000
#define NEDGE 800000
#define DFACT 768
#define HID   128
#define NB    256

#define PITCH 40                 // halves per smem row (conflict-free frags)
#define STGH  (128 * PITCH)      // halves per stage
#define G1_SMEM ((2 + 3) * STGH * 2)   // A x2, B x3
#define G2_SMEM ((3 + 3) * STGH * 2)   // A x3, B x3
#define SCAN_BS 256
#define FOFF 512                 // bsum offset for fact-relation blocks

// ---------------- scratch (device globals; no allocation allowed) ----------
__device__ float g_wfc[NEDGE];
__device__ float g_wcf[NEDGE];
__device__ float g_dfc_s[NFACT];
__device__ float g_dfc_d[NCOMP];
__device__ float g_dcf_s[NCOMP];
__device__ float g_dcf_d[NFACT];
__device__ __align__(16) __half g_W1t[(size_t)HID * DFACT];  // [n][k] fp16
__device__ __align__(16) __half g_W2t[(size_t)HID * HID];    // [n][k] fp16
__device__ __align__(16) __half g_H1[(size_t)NFACT * HID];
__device__ __align__(16) __half g_c1h[(size_t)NCOMP * HID];  // relu(agg+b1) fp16
__device__ __align__(16) __half g_H2[(size_t)NCOMP * HID];
__device__ float g_psum[NB];
__device__ float g_pcnt[NB];
// CSR scratch
__device__ int   g_cntc[NCOMP];
__device__ int   g_cntf[NFACT];
__device__ int   g_bsum[1024];
__device__ int   g_rpc[NCOMP + 1];
__device__ int   g_rpf[NFACT + 1];
__device__ int   g_curc[NCOMP];
__device__ int   g_curf[NFACT];
__device__ uint2 g_pfc[NEDGE];
__device__ uint2 g_pcf[NEDGE];

// ---------------- helpers --------------------------------------------------
__device__ __forceinline__ void mma_f16(float* c, const uint32_t* a, const uint32_t* b) {
    asm volatile(
        "mma.sync.aligned.m16n8k16.row.col.f32.f16.f16.f32 "
        "{%0,%1,%2,%3}, {%4,%5,%6,%7}, {%8,%9}, {%0,%1,%2,%3};"
        : "+f"(c[0]), "+f"(c[1]), "+f"(c[2]), "+f"(c[3])
        : "r"(a[0]), "r"(a[1]), "r"(a[2]), "r"(a[3]), "r"(b[0]), "r"(b[1]));
}
#define CP_COMMIT() asm volatile("cp.async.commit_group;")
#define CP_WAIT1()  asm volatile("cp.async.wait_group 1;")
__device__ __forceinline__ void cpa16(__half* sp, const __half* gp) {
    uint32_t sa = (uint32_t)__cvta_generic_to_shared(sp);
    asm volatile("cp.async.cg.shared.global [%0], [%1], 16;" :: "r"(sa), "l"(gp));
}
__device__ __forceinline__ float inv_sqrt_deg(float d) {
    return (d > 0.f) ? rsqrtf(d) : 0.f;
}

// ---------------- fused edge kernels ---------------------------------------
// both relations in one launch: gate + degrees + CSR histogram
__global__ void gate_deg2_kernel(const float* __restrict__ eaA, const float* __restrict__ eaB,
                                 const int* __restrict__ srcA, const int* __restrict__ dstA,
                                 const int* __restrict__ srcB, const int* __restrict__ dstB,
                                 const float* __restrict__ Wm, const float* __restrict__ bm,
                                 float* __restrict__ wA, float* __restrict__ wB,
                                 float* __restrict__ degsA, float* __restrict__ degdA,
                                 float* __restrict__ degsB, float* __restrict__ degdB,
                                 int* __restrict__ cntA, int* __restrict__ cntB) {
    int i = blockIdx.x * blockDim.x + threadIdx.x;
    int e = (i < NEDGE) ? i : i - NEDGE;
    if (i >= 2 * NEDGE) return;
    const float* ea = (i < NEDGE) ? eaA : eaB;
    float a0 = ea[2 * e + 0], a1 = ea[2 * e + 1];
    float z  = a0 * Wm[0] + a1 * Wm[1] + bm[0];
    float ww = 1.f / (1.f + expf(-z));
    if (i < NEDGE) {
        wA[e] = ww;
        int d = dstA[e];
        atomicAdd(&degsA[srcA[e]], ww);
        atomicAdd(&degdA[d], ww);
        atomicAdd(&cntA[d], 1);
    } else {
        wB[e] = ww;
        int d = dstB[e];
        atomicAdd(&degsB[srcB[e]], ww);
        atomicAdd(&degdB[d], ww);
        atomicAdd(&cntB[d], 1);
    }
}

// transpose + fp16-round weights: W[k][n] f32 -> Wt[n][k] fp16
__global__ void prep_w_kernel(const float* __restrict__ W1, const float* __restrict__ W2,
                              __half* __restrict__ W1t, __half* __restrict__ W2t) {
    int i = blockIdx.x * blockDim.x + threadIdx.x;
    int n1 = DFACT * HID;
    if (i < n1) {
        int k = i >> 7, n = i & 127;
        W1t[(size_t)n * DFACT + k] = __float2half_rn(W1[i]);
    } else if (i < n1 + HID * HID) {
        int j = i - n1;
        int k = j >> 7, n = j & 127;
        W2t[(size_t)n * HID + k] = __float2half_rn(W2[j]);
    }
}

// ---------------- CSR build (merged grids) ----------------------------------
__global__ void scan_bsum2_kernel(const int* __restrict__ cntc, const int* __restrict__ cntf,
                                  int nbC, int* __restrict__ bsum) {
    __shared__ int sh[SCAN_BS];
    bool isC = (int)blockIdx.x < nbC;
    const int* cnt = isC ? cntc : cntf;
    int n   = isC ? NCOMP : NFACT;
    int bid = isC ? blockIdx.x : blockIdx.x - nbC;
    int i = bid * SCAN_BS + threadIdx.x;
    sh[threadIdx.x] = (i < n) ? cnt[i] : 0;
    __syncthreads();
    for (int o = SCAN_BS / 2; o; o >>= 1) {
        if (threadIdx.x < o) sh[threadIdx.x] += sh[threadIdx.x + o];
        __syncthreads();
    }
    if (threadIdx.x == 0) bsum[(isC ? 0 : FOFF) + bid] = sh[0];
}

__global__ void scan_tops2_kernel(int* __restrict__ bsum, int nbC, int nbF,
                                  int* __restrict__ rpc, int* __restrict__ rpf) {
    __shared__ int sh[1024];
    bool isC = (blockIdx.x == 0);
    int* bs = bsum + (isC ? 0 : FOFF);
    int nb  = isC ? nbC : nbF;
    int tid = threadIdx.x;
    int v = (tid < nb) ? bs[tid] : 0;
    sh[tid] = v;
    __syncthreads();
    for (int o = 1; o < 1024; o <<= 1) {
        int t = (tid >= o) ? sh[tid - o] : 0;
        __syncthreads();
        sh[tid] += t;
        __syncthreads();
    }
    if (tid < nb) bs[tid] = sh[tid] - v;
    if (tid == 0) { if (isC) rpc[NCOMP] = sh[1023]; else rpf[NFACT] = sh[1023]; }
}

__global__ void scan_write2_kernel(const int* __restrict__ cntc, const int* __restrict__ cntf,
                                   const int* __restrict__ bsum, int nbC,
                                   int* __restrict__ rpc, int* __restrict__ curc,
                                   int* __restrict__ rpf, int* __restrict__ curf) {
    __shared__ int sh[SCAN_BS];
    bool isC = (int)blockIdx.x < nbC;
    const int* cnt = isC ? cntc : cntf;
    int n   = isC ? NCOMP : NFACT;
    int bid = isC ? blockIdx.x : blockIdx.x - nbC;
    int* rowptr = isC ? rpc : rpf;
    int* cur    = isC ? curc : curf;
    int bofs = (isC ? 0 : FOFF) + bid;
    int tid = threadIdx.x;
    int i = bid * SCAN_BS + tid;
    int v = (i < n) ? cnt[i] : 0;
    sh[tid] = v;
    __syncthreads();
    for (int o = 1; o < SCAN_BS; o <<= 1) {
        int t = (tid >= o) ? sh[tid - o] : 0;
        __syncthreads();
        sh[tid] += t;
        __syncthreads();
    }
    if (i < n) {
        int ex = sh[tid] - v + bsum[bofs];
        rowptr[i] = ex;
        cur[i] = ex;
    }
}

// both relations in one launch
__global__ void scatter2_kernel(const int* __restrict__ srcA, const int* __restrict__ dstA,
                                const float* __restrict__ wA, const float* __restrict__ degsA,
                                int* __restrict__ curA, uint2* __restrict__ pkA,
                                const int* __restrict__ srcB, const int* __restrict__ dstB,
                                const float* __restrict__ wB, const float* __restrict__ degsB,
                                int* __restrict__ curB, uint2* __restrict__ pkB) {
    int i = blockIdx.x * blockDim.x + threadIdx.x;
    if (i >= 2 * NEDGE) return;
    if (i < NEDGE) {
        int e = i, d = dstA[e], s = srcA[e];
        int pos = atomicAdd(&curA[d], 1);
        pkA[pos] = make_uint2((uint32_t)s,
                              __float_as_uint(wA[e] * inv_sqrt_deg(degsA[s])));
    } else {
        int e = i - NEDGE, d = dstB[e], s = srcB[e];
        int pos = atomicAdd(&curB[d], 1);
        pkB[pos] = make_uint2((uint32_t)s,
                              __float_as_uint(wB[e] * inv_sqrt_deg(degsB[s])));
    }
}

// ---------------- gather (warp per node, x4 unrolled) -----------------------
// MODE 0: out_h[node] = fp16(relu(acc*dd + bias[dim]))          (c1 for GEMM2)
// MODE 1: pooled classifier: s = sum_dim relu(acc*dd + b2)*Wc -> psum[batch]
template <int MODE>
__global__ void gather_kernel(__half* __restrict__ outh, const __half* __restrict__ h,
                              const uint2* __restrict__ packed,
                              const int* __restrict__ rowptr,
                              const float* __restrict__ deg_d,
                              const float* __restrict__ bias,
                              const float* __restrict__ Wc,
                              const int* __restrict__ batch,
                              float* __restrict__ psum, float* __restrict__ pcnt,
                              int n) {
    int node = blockIdx.x * (blockDim.x >> 5) + (threadIdx.x >> 5);
    if (node >= n) return;
    int lane = threadIdx.x & 31;
    int r0 = __ldg(rowptr + node), r1 = __ldg(rowptr + node + 1);
    float4 acc = make_float4(0.f, 0.f, 0.f, 0.f);
    for (int base = r0; base < r1; base += 32) {
        int nit = min(32, r1 - base);
        uint2 meta = (lane < nit) ? __ldg(packed + base + lane) : make_uint2(0u, 0u);
        int nit4 = (nit + 3) & ~3;
        for (int j = 0; j < nit4; j += 4) {
            int   s0 = __shfl_sync(0xffffffffu, (int)meta.x, j + 0);
            int   s1 = __shfl_sync(0xffffffffu, (int)meta.x, (j + 1) & 31);
            int   s2 = __shfl_sync(0xffffffffu, (int)meta.x, (j + 2) & 31);
            int   s3 = __shfl_sync(0xffffffffu, (int)meta.x, (j + 3) & 31);
            float w0 = __uint_as_float(__shfl_sync(0xffffffffu, meta.y, j + 0));
            float w1 = __uint_as_float(__shfl_sync(0xffffffffu, meta.y, (j + 1) & 31));
            float w2 = __uint_as_float(__shfl_sync(0xffffffffu, meta.y, (j + 2) & 31));
            float w3 = __uint_as_float(__shfl_sync(0xffffffffu, meta.y, (j + 3) & 31));
            uint2 v0 = *reinterpret_cast<const uint2*>(h + (size_t)s0 * 128 + lane * 4);
            uint2 v1 = *reinterpret_cast<const uint2*>(h + (size_t)s1 * 128 + lane * 4);
            uint2 v2 = *reinterpret_cast<const uint2*>(h + (size_t)s2 * 128 + lane * 4);
            uint2 v3 = *reinterpret_cast<const uint2*>(h + (size_t)s3 * 128 + lane * 4);
#define ACC(V, W)                                                              \
            {                                                                  \
                float2 fa = __half22float2(*reinterpret_cast<__half2*>(&V.x)); \
                float2 fb = __half22float2(*reinterpret_cast<__half2*>(&V.y)); \
                acc.x += (W) * fa.x; acc.y += (W) * fa.y;                      \
                acc.z += (W) * fb.x; acc.w += (W) * fb.y;                      \
            }
            ACC(v0, w0) ACC(v1, w1) ACC(v2, w2) ACC(v3, w3)
#undef ACC
        }
    }
    float dd = inv_sqrt_deg(__ldg(deg_d + node));
    acc.x *= dd; acc.y *= dd; acc.z *= dd; acc.w *= dd;
    float4 bb = reinterpret_cast<const float4*>(bias)[lane];
    acc.x = fmaxf(acc.x + bb.x, 0.f);
    acc.y = fmaxf(acc.y + bb.y, 0.f);
    acc.z = fmaxf(acc.z + bb.z, 0.f);
    acc.w = fmaxf(acc.w + bb.w, 0.f);
    if (MODE == 0) {
        __half2 o0 = __floats2half2_rn(acc.x, acc.y);
        __half2 o1 = __floats2half2_rn(acc.z, acc.w);
        *reinterpret_cast<uint2*>(outh + (size_t)node * 128 + lane * 4) =
            make_uint2(*reinterpret_cast<uint32_t*>(&o0), *reinterpret_cast<uint32_t*>(&o1));
    } else {
        float4 wc = reinterpret_cast<const float4*>(Wc)[lane];
        float s = acc.x * wc.x + acc.y * wc.y + acc.z * wc.z + acc.w * wc.w;
#pragma unroll
        for (int o = 16; o; o >>= 1) s += __shfl_down_sync(0xffffffffu, s, o);
        if (lane == 0) {
            int g = batch[node];
            atomicAdd(&psum[g], s);
            atomicAdd(&pcnt[g], 1.f);
        }
    }
}

// ---------------- GEMM1: A f32 (cvt in reg), B fp16 cp.async ----------------
// one __syncthreads per K-tile; A double-buffered, B triple-buffered.
__global__ __launch_bounds__(256) void hgemm1_kernel(
        const float* __restrict__ A, const __half* __restrict__ Bt,
        __half* __restrict__ C, int M, int K) {
    extern __shared__ __half hsm[];
    __half* Asm = hsm;              // 2 stages
    __half* Bsm = hsm + 2 * STGH;   // 3 stages

    const int tid  = threadIdx.x;
    const int wid  = tid >> 5;
    const int lane = tid & 31;
    const int gid  = lane >> 2;
    const int tid4 = lane & 3;
    const int wm   = (wid & 3) * 32;
    const int wn   = (wid >> 2) * 64;
    const int row0 = blockIdx.x * 128;
    const int nt   = K >> 5;

    float acc[2][8][4] = {};
    int aR[4]; const int aC = (tid & 7) * 4;
    int bR[2]; const int bK = (tid & 3) * 8;
#pragma unroll
    for (int i = 0; i < 4; i++) aR[i] = (tid + i * 256) >> 3;
#pragma unroll
    for (int i = 0; i < 2; i++) bR[i] = (tid + i * 256) >> 2;

    float4 av[4];
#define G_LDG(t)                                                               \
    do {                                                                       \
        int k0 = (t) * 32;                                                     \
        _Pragma("unroll")                                                      \
        for (int i = 0; i < 4; i++) {                                          \
            int r = row0 + aR[i];                                              \
            av[i] = (r < M) ? *reinterpret_cast<const float4*>(                \
                                  A + (size_t)r * K + k0 + aC)                 \
                            : make_float4(0.f, 0.f, 0.f, 0.f);                 \
        }                                                                      \
    } while (0)
#define G_CPB(t)                                                               \
    do {                                                                       \
        int k0 = (t) * 32;                                                     \
        __half* bs = Bsm + ((t) % 3) * STGH;                                   \
        _Pragma("unroll")                                                      \
        for (int i = 0; i < 2; i++)                                            \
            cpa16(bs + bR[i] * PITCH + bK, Bt + (size_t)bR[i] * K + k0 + bK);  \
    } while (0)
#define G_STS(t)                                                               \
    do {                                                                       \
        __half* as = Asm + ((t) & 1) * STGH;                                   \
        _Pragma("unroll")                                                      \
        for (int i = 0; i < 4; i++) {                                          \
            __half2 h0 = __floats2half2_rn(av[i].x, av[i].y);                  \
            __half2 h1 = __floats2half2_rn(av[i].z, av[i].w);                  \
            *reinterpret_cast<uint2*>(as + aR[i] * PITCH + aC) =               \
                make_uint2(*reinterpret_cast<uint32_t*>(&h0),                  \
                           *reinterpret_cast<uint32_t*>(&h1));                 \
        }                                                                      \
    } while (0)

    G_LDG(0);
    G_CPB(0); CP_COMMIT();

    for (int t = 0; t < nt; t++) {
        G_STS(t);
        if (t + 1 < nt) { G_LDG(t + 1); G_CPB(t + 1); }
        CP_COMMIT();
        CP_WAIT1();
        __syncthreads();

        const __half* as = Asm + (t & 1) * STGH;
        const __half* bs = Bsm + (t % 3) * STGH;
#pragma unroll
        for (int kk = 0; kk < 32; kk += 16) {
            uint32_t afr[2][4], bfr[8][2];
#pragma unroll
            for (int mi = 0; mi < 2; mi++) {
                int r = wm + mi * 16 + gid;
                afr[mi][0] = *reinterpret_cast<const uint32_t*>(&as[r * PITCH + kk + 2 * tid4]);
                afr[mi][1] = *reinterpret_cast<const uint32_t*>(&as[(r + 8) * PITCH + kk + 2 * tid4]);
                afr[mi][2] = *reinterpret_cast<const uint32_t*>(&as[r * PITCH + kk + 8 + 2 * tid4]);
                afr[mi][3] = *reinterpret_cast<const uint32_t*>(&as[(r + 8) * PITCH + kk + 8 + 2 * tid4]);
            }
#pragma unroll
            for (int ni = 0; ni < 8; ni++) {
                int c = wn + ni * 8 + gid;
                bfr[ni][0] = *reinterpret_cast<const uint32_t*>(&bs[c * PITCH + kk + 2 * tid4]);
                bfr[ni][1] = *reinterpret_cast<const uint32_t*>(&bs[c * PITCH + kk + 8 + 2 * tid4]);
            }
#pragma unroll
            for (int mi = 0; mi < 2; mi++)
#pragma unroll
                for (int ni = 0; ni < 8; ni++)
                    mma_f16(acc[mi][ni], afr[mi], bfr[ni]);
        }
    }

#pragma unroll
    for (int mi = 0; mi < 2; mi++)
#pragma unroll
        for (int ni = 0; ni < 8; ni++) {
            int r1 = row0 + wm + mi * 16 + gid;
            int r2 = r1 + 8;
            int c  = wn + ni * 8 + tid4 * 2;
            if (r1 < M)
                *reinterpret_cast<__half2*>(C + (size_t)r1 * 128 + c) =
                    __floats2half2_rn(acc[mi][ni][0], acc[mi][ni][1]);
            if (r2 < M)
                *reinterpret_cast<__half2*>(C + (size_t)r2 * 128 + c) =
                    __floats2half2_rn(acc[mi][ni][2], acc[mi][ni][3]);
        }
#undef G_LDG
#undef G_CPB
#undef G_STS
}

// ---------------- GEMM2: both operands fp16 via cp.async --------------------
__global__ __launch_bounds__(256) void hgemm2_kernel(
        const __half* __restrict__ A, const __half* __restrict__ Bt,
        __half* __restrict__ C, int M, int K) {
    extern __shared__ __half hsm[];
    __half* Asm = hsm;              // 3 stages
    __half* Bsm = hsm + 3 * STGH;   // 3 stages

    const int tid  = threadIdx.x;
    const int wid  = tid >> 5;
    const int lane = tid & 31;
    const int gid  = lane >> 2;
    const int tid4 = lane & 3;
    const int wm   = (wid & 3) * 32;
    const int wn   = (wid >> 2) * 64;
    const int row0 = blockIdx.x * 128;
    const int nt   = K >> 5;

    float acc[2][8][4] = {};
    int xR[2]; const int xK = (tid & 3) * 8;
#pragma unroll
    for (int i = 0; i < 2; i++) xR[i] = (tid + i * 256) >> 2;

#define G2_CP(t)                                                               \
    do {                                                                       \
        int k0 = (t) * 32;                                                     \
        __half* as = Asm + ((t) % 3) * STGH;                                   \
        __half* bs = Bsm + ((t) % 3) * STGH;                                   \
        _Pragma("unroll")                                                      \
        for (int i = 0; i < 2; i++) {                                          \
            int r = row0 + xR[i];                                              \
            const __half* gp = (r < M) ? A + (size_t)r * K + k0 + xK           \
                                       : A + k0 + xK;                          \
            cpa16(as + xR[i] * PITCH + xK, gp);                                \
            cpa16(bs + xR[i] * PITCH + xK, Bt + (size_t)xR[i] * K + k0 + xK);  \
        }                                                                      \
    } while (0)

    G2_CP(0); CP_COMMIT();

    for (int t = 0; t < nt; t++) {
        if (t + 1 < nt) G2_CP(t + 1);
        CP_COMMIT();
        CP_WAIT1();
        __syncthreads();

        const __half* as = Asm + (t % 3) * STGH;
        const __half* bs = Bsm + (t % 3) * STGH;
#pragma unroll
        for (int kk = 0; kk < 32; kk += 16) {
            uint32_t afr[2][4], bfr[8][2];
#pragma unroll
            for (int mi = 0; mi < 2; mi++) {
                int r = wm + mi * 16 + gid;
                afr[mi][0] = *reinterpret_cast<const uint32_t*>(&as[r * PITCH + kk + 2 * tid4]);
                afr[mi][1] = *reinterpret_cast<const uint32_t*>(&as[(r + 8) * PITCH + kk + 2 * tid4]);
                afr[mi][2] = *reinterpret_cast<const uint32_t*>(&as[r * PITCH + kk + 8 + 2 * tid4]);
                afr[mi][3] = *reinterpret_cast<const uint32_t*>(&as[(r + 8) * PITCH + kk + 8 + 2 * tid4]);
            }
#pragma unroll
            for (int ni = 0; ni < 8; ni++) {
                int c = wn + ni * 8 + gid;
                bfr[ni][0] = *reinterpret_cast<const uint32_t*>(&bs[c * PITCH + kk + 2 * tid4]);
                bfr[ni][1] = *reinterpret_cast<const uint32_t*>(&bs[c * PITCH + kk + 8 + 2 * tid4]);
            }
#pragma unroll
            for (int mi = 0; mi < 2; mi++)
#pragma unroll
                for (int ni = 0; ni < 8; ni++)
                    mma_f16(acc[mi][ni], afr[mi], bfr[ni]);
        }
    }

#pragma unroll
    for (int mi = 0; mi < 2; mi++)
#pragma unroll
        for (int ni = 0; ni < 8; ni++) {
            int r1 = row0 + wm + mi * 16 + gid;
            int r2 = r1 + 8;
            int c  = wn + ni * 8 + tid4 * 2;
            if (r1 < M)
                *reinterpret_cast<__half2*>(C + (size_t)r1 * 128 + c) =
                    __floats2half2_rn(acc[mi][ni][0], acc[mi][ni][1]);
            if (r2 < M)
                *reinterpret_cast<__half2*>(C + (size_t)r2 * 128 + c) =
                    __floats2half2_rn(acc[mi][ni][2], acc[mi][ni][3]);
        }
#undef G2_CP
}

__global__ void final_kernel(const float* __restrict__ psum,
                             const float* __restrict__ pcnt,
                             const float* __restrict__ bc,
                             float* __restrict__ out) {
    int g = threadIdx.x;
    if (g < NB) out[g] = psum[g] / fmaxf(pcnt[g], 1.f) + bc[0];
}

// ---------------- launch ---------------------------------------------------
extern "C" void kernel_launch(void* const* d_in, const int* in_sizes, int n_in,
                              void* d_out, int out_size) {
    const float* x_fact     = (const float*)d_in[0];
    const float* ea_fc      = (const float*)d_in[2];
    const float* ea_cf      = (const float*)d_in[3];
    const int*   fc_src     = (const int*)d_in[4];
    const int*   fc_dst     = (const int*)d_in[5];
    const int*   cf_src     = (const int*)d_in[6];
    const int*   cf_dst     = (const int*)d_in[7];
    const int*   batch_fact = (const int*)d_in[8];
    const float* Wm         = (const float*)d_in[9];
    const float* bm         = (const float*)d_in[10];
    const float* W1_fc      = (const float*)d_in[11];
    const float* b1_fc      = (const float*)d_in[12];
    const float* W2_cf      = (const float*)d_in[17];
    const float* b2_cf      = (const float*)d_in[18];
    const float* Wc         = (const float*)d_in[19];
    const float* bc         = (const float*)d_in[20];
    float* out = (float*)d_out;

    float *wfc, *wcf, *dfcs, *dfcd, *dcfs, *dcfd, *psum, *pcnt;
    __half *W1t, *W2t, *H1, *c1h, *H2;
    int *cntc, *cntf, *bsum, *rpc, *rpf, *curc, *curf;
    uint2 *pfc, *pcf;
    cudaGetSymbolAddress((void**)&wfc,  g_wfc);
    cudaGetSymbolAddress((void**)&wcf,  g_wcf);
    cudaGetSymbolAddress((void**)&dfcs, g_dfc_s);
    cudaGetSymbolAddress((void**)&dfcd, g_dfc_d);
    cudaGetSymbolAddress((void**)&dcfs, g_dcf_s);
    cudaGetSymbolAddress((void**)&dcfd, g_dcf_d);
    cudaGetSymbolAddress((void**)&W1t,  g_W1t);
    cudaGetSymbolAddress((void**)&W2t,  g_W2t);
    cudaGetSymbolAddress((void**)&H1,   g_H1);
    cudaGetSymbolAddress((void**)&c1h,  g_c1h);
    cudaGetSymbolAddress((void**)&H2,   g_H2);
    cudaGetSymbolAddress((void**)&psum, g_psum);
    cudaGetSymbolAddress((void**)&pcnt, g_pcnt);
    cudaGetSymbolAddress((void**)&cntc, g_cntc);
    cudaGetSymbolAddress((void**)&cntf, g_cntf);
    cudaGetSymbolAddress((void**)&bsum, g_bsum);
    cudaGetSymbolAddress((void**)&rpc,  g_rpc);
    cudaGetSymbolAddress((void**)&rpf,  g_rpf);
    cudaGetSymbolAddress((void**)&curc, g_curc);
    cudaGetSymbolAddress((void**)&curf, g_curf);
    cudaGetSymbolAddress((void**)&pfc,  g_pfc);
    cudaGetSymbolAddress((void**)&pcf,  g_pcf);

    cudaFuncSetAttribute(hgemm1_kernel,
                         cudaFuncAttributeMaxDynamicSharedMemorySize, G1_SMEM);
    cudaFuncSetAttribute(hgemm2_kernel,
                         cudaFuncAttributeMaxDynamicSharedMemorySize, G2_SMEM);

    cudaMemsetAsync(dfcs, 0, NFACT * sizeof(float));
    cudaMemsetAsync(dfcd, 0, NCOMP * sizeof(float));
    cudaMemsetAsync(dcfs, 0, NCOMP * sizeof(float));
    cudaMemsetAsync(dcfd, 0, NFACT * sizeof(float));
    cudaMemsetAsync(cntc, 0, NCOMP * sizeof(int));
    cudaMemsetAsync(cntf, 0, NFACT * sizeof(int));
    cudaMemsetAsync(psum, 0, NB * sizeof(float));
    cudaMemsetAsync(pcnt, 0, NB * sizeof(float));

    const int nbC = (NCOMP + SCAN_BS - 1) / SCAN_BS;   // 40
    const int nbF = (NFACT + SCAN_BS - 1) / SCAN_BS;   // 391

    // 1: gates + degrees + histograms, both relations
    gate_deg2_kernel<<<(2 * NEDGE + 255) / 256, 256>>>(
        ea_fc, ea_cf, fc_src, fc_dst, cf_src, cf_dst, Wm, bm,
        wfc, wcf, dfcs, dfcd, dcfs, dcfd, cntc, cntf);
    // 2: weights transpose + fp16 round
    prep_w_kernel<<<(DFACT * HID + HID * HID + 255) / 256, 256>>>(W1_fc, W2_cf, W1t, W2t);
    // 3: block sums for both scans
    scan_bsum2_kernel<<<nbC + nbF, SCAN_BS>>>(cntc, cntf, nbC, bsum);
    // 4: GEMM1 (profiled slot)
    hgemm1_kernel<<<(NFACT + 127) / 128, 256, G1_SMEM>>>(x_fact, W1t, H1, NFACT, DFACT);
    // 5-6: finish scans
    scan_tops2_kernel<<<2, 1024>>>(bsum, nbC, nbF, rpc, rpf);
    scan_write2_kernel<<<nbC + nbF, SCAN_BS>>>(cntc, cntf, bsum, nbC,
                                               rpc, curc, rpf, curf);
    // 7: scatter both relations
    scatter2_kernel<<<(2 * NEDGE + 255) / 256, 256>>>(
        fc_src, fc_dst, wfc, dfcs, curc, pfc,
        cf_src, cf_dst, wcf, dcfs, curf, pcf);
    // 8: gather1 -> c1h = fp16(relu(agg + b1))
    gather_kernel<0><<<(NCOMP + 7) / 8, 256>>>(c1h, H1, pfc, rpc, dfcd,
                                               b1_fc, nullptr, nullptr,
                                               nullptr, nullptr, NCOMP);
    // 9: GEMM2 (pure fp16)
    hgemm2_kernel<<<(NCOMP + 127) / 128, 256, G2_SMEM>>>(c1h, W2t, H2, NCOMP, HID);
    // 10: gather2 + relu + classifier dot + pool (fused)
    gather_kernel<1><<<(NFACT + 7) / 8, 256>>>(nullptr, H2, pcf, rpf, dcfd,
                                               b2_cf, Wc, batch_fact,
                                               psum, pcnt, NFACT);
    // 11: final
    final_kernel<<<1, NB>>>(psum, pcnt, bc, out);
}

// round 13
// speedup vs baseline: 1.2548x; 1.2548x over previous
#include <cuda_runtime.h>
#include <cuda_fp16.h>
#include <cstdint>

#define NFACT 100000
#define NCOMP 10000
#define NEDGE 800000
#define DFACT 768
#define HID   128
#define NB    256

#define PITCH 40                 // halves per smem row; 80B stride -> ldmatrix conflict-free
#define STGH  (128 * PITCH)      // halves per stage
#define SCAN_BS 256
#define FOFF 512                 // bsum offset for fact-relation blocks

// ---------------- scratch (device globals; no allocation allowed) ----------
__device__ float g_wfc[NEDGE];
__device__ float g_wcf[NEDGE];
__device__ float g_dfc_s[NFACT];
__device__ float g_dfc_d[NCOMP];
__device__ float g_dcf_s[NCOMP];
__device__ float g_dcf_d[NFACT];
__device__ __align__(16) __half g_W1t[(size_t)HID * DFACT];  // [n][k] fp16
__device__ __align__(16) __half g_W2t[(size_t)HID * HID];    // [n][k] fp16
__device__ __align__(16) __half g_H1[(size_t)NFACT * HID];
__device__ __align__(16) __half g_c1h[(size_t)NCOMP * HID];  // relu(agg+b1) fp16
__device__ __align__(16) __half g_H2[(size_t)NCOMP * HID];
__device__ float g_psum[NB];
__device__ float g_pcnt[NB];
// CSR scratch
__device__ int   g_cntc[NCOMP];
__device__ int   g_cntf[NFACT];
__device__ int   g_bsum[1024];
__device__ int   g_rpc[NCOMP + 1];
__device__ int   g_rpf[NFACT + 1];
__device__ int   g_curc[NCOMP];
__device__ int   g_curf[NFACT];
__device__ uint2 g_pfc[NEDGE];
__device__ uint2 g_pcf[NEDGE];

// ---------------- helpers --------------------------------------------------
__device__ __forceinline__ void mma_f16(float* c, const uint32_t* a, const uint32_t* b) {
    asm volatile(
        "mma.sync.aligned.m16n8k16.row.col.f32.f16.f16.f32 "
        "{%0,%1,%2,%3}, {%4,%5,%6,%7}, {%8,%9}, {%0,%1,%2,%3};"
        : "+f"(c[0]), "+f"(c[1]), "+f"(c[2]), "+f"(c[3])
        : "r"(a[0]), "r"(a[1]), "r"(a[2]), "r"(a[3]), "r"(b[0]), "r"(b[1]));
}
__device__ __forceinline__ void ldsm_x4(uint32_t& r0, uint32_t& r1, uint32_t& r2,
                                        uint32_t& r3, const __half* p) {
    uint32_t a = (uint32_t)__cvta_generic_to_shared(p);
    asm volatile("ldmatrix.sync.aligned.m8n8.x4.shared.b16 {%0,%1,%2,%3}, [%4];"
                 : "=r"(r0), "=r"(r1), "=r"(r2), "=r"(r3) : "r"(a));
}
#define CP_COMMIT() asm volatile("cp.async.commit_group;")
#define CP_WAIT1()  asm volatile("cp.async.wait_group 1;")
__device__ __forceinline__ void cpa16(__half* sp, const __half* gp) {
    uint32_t sa = (uint32_t)__cvta_generic_to_shared(sp);
    asm volatile("cp.async.cg.shared.global [%0], [%1], 16;" :: "r"(sa), "l"(gp));
}
__device__ __forceinline__ float inv_sqrt_deg(float d) {
    return (d > 0.f) ? rsqrtf(d) : 0.f;
}

// ---------------- fused edge kernels ---------------------------------------
__global__ void gate_deg2_kernel(const float* __restrict__ eaA, const float* __restrict__ eaB,
                                 const int* __restrict__ srcA, const int* __restrict__ dstA,
                                 const int* __restrict__ srcB, const int* __restrict__ dstB,
                                 const float* __restrict__ Wm, const float* __restrict__ bm,
                                 float* __restrict__ wA, float* __restrict__ wB,
                                 float* __restrict__ degsA, float* __restrict__ degdA,
                                 float* __restrict__ degsB, float* __restrict__ degdB,
                                 int* __restrict__ cntA, int* __restrict__ cntB) {
    int i = blockIdx.x * blockDim.x + threadIdx.x;
    int e = (i < NEDGE) ? i : i - NEDGE;
    if (i >= 2 * NEDGE) return;
    const float* ea = (i < NEDGE) ? eaA : eaB;
    float a0 = ea[2 * e + 0], a1 = ea[2 * e + 1];
    float z  = a0 * Wm[0] + a1 * Wm[1] + bm[0];
    float ww = 1.f / (1.f + expf(-z));
    if (i < NEDGE) {
        wA[e] = ww;
        int d = dstA[e];
        atomicAdd(&degsA[srcA[e]], ww);
        atomicAdd(&degdA[d], ww);
        atomicAdd(&cntA[d], 1);
    } else {
        wB[e] = ww;
        int d = dstB[e];
        atomicAdd(&degsB[srcB[e]], ww);
        atomicAdd(&degdB[d], ww);
        atomicAdd(&cntB[d], 1);
    }
}

__global__ void prep_w_kernel(const float* __restrict__ W1, const float* __restrict__ W2,
                              __half* __restrict__ W1t, __half* __restrict__ W2t) {
    int i = blockIdx.x * blockDim.x + threadIdx.x;
    int n1 = DFACT * HID;
    if (i < n1) {
        int k = i >> 7, n = i & 127;
        W1t[(size_t)n * DFACT + k] = __float2half_rn(W1[i]);
    } else if (i < n1 + HID * HID) {
        int j = i - n1;
        int k = j >> 7, n = j & 127;
        W2t[(size_t)n * HID + k] = __float2half_rn(W2[j]);
    }
}

// ---------------- CSR build (merged grids) ----------------------------------
__global__ void scan_bsum2_kernel(const int* __restrict__ cntc, const int* __restrict__ cntf,
                                  int nbC, int* __restrict__ bsum) {
    __shared__ int sh[SCAN_BS];
    bool isC = (int)blockIdx.x < nbC;
    const int* cnt = isC ? cntc : cntf;
    int n   = isC ? NCOMP : NFACT;
    int bid = isC ? blockIdx.x : blockIdx.x - nbC;
    int i = bid * SCAN_BS + threadIdx.x;
    sh[threadIdx.x] = (i < n) ? cnt[i] : 0;
    __syncthreads();
    for (int o = SCAN_BS / 2; o; o >>= 1) {
        if (threadIdx.x < o) sh[threadIdx.x] += sh[threadIdx.x + o];
        __syncthreads();
    }
    if (threadIdx.x == 0) bsum[(isC ? 0 : FOFF) + bid] = sh[0];
}

__global__ void scan_tops2_kernel(int* __restrict__ bsum, int nbC, int nbF,
                                  int* __restrict__ rpc, int* __restrict__ rpf) {
    __shared__ int sh[1024];
    bool isC = (blockIdx.x == 0);
    int* bs = bsum + (isC ? 0 : FOFF);
    int nb  = isC ? nbC : nbF;
    int tid = threadIdx.x;
    int v = (tid < nb) ? bs[tid] : 0;
    sh[tid] = v;
    __syncthreads();
    for (int o = 1; o < 1024; o <<= 1) {
        int t = (tid >= o) ? sh[tid - o] : 0;
        __syncthreads();
        sh[tid] += t;
        __syncthreads();
    }
    if (tid < nb) bs[tid] = sh[tid] - v;
    if (tid == 0) { if (isC) rpc[NCOMP] = sh[1023]; else rpf[NFACT] = sh[1023]; }
}

__global__ void scan_write2_kernel(const int* __restrict__ cntc, const int* __restrict__ cntf,
                                   const int* __restrict__ bsum, int nbC,
                                   int* __restrict__ rpc, int* __restrict__ curc,
                                   int* __restrict__ rpf, int* __restrict__ curf) {
    __shared__ int sh[SCAN_BS];
    bool isC = (int)blockIdx.x < nbC;
    const int* cnt = isC ? cntc : cntf;
    int n   = isC ? NCOMP : NFACT;
    int bid = isC ? blockIdx.x : blockIdx.x - nbC;
    int* rowptr = isC ? rpc : rpf;
    int* cur    = isC ? curc : curf;
    int bofs = (isC ? 0 : FOFF) + bid;
    int tid = threadIdx.x;
    int i = bid * SCAN_BS + tid;
    int v = (i < n) ? cnt[i] : 0;
    sh[tid] = v;
    __syncthreads();
    for (int o = 1; o < SCAN_BS; o <<= 1) {
        int t = (tid >= o) ? sh[tid - o] : 0;
        __syncthreads();
        sh[tid] += t;
        __syncthreads();
    }
    if (i < n) {
        int ex = sh[tid] - v + bsum[bofs];
        rowptr[i] = ex;
        cur[i] = ex;
    }
}

__global__ void scatter2_kernel(const int* __restrict__ srcA, const int* __restrict__ dstA,
                                const float* __restrict__ wA, const float* __restrict__ degsA,
                                int* __restrict__ curA, uint2* __restrict__ pkA,
                                const int* __restrict__ srcB, const int* __restrict__ dstB,
                                const float* __restrict__ wB, const float* __restrict__ degsB,
                                int* __restrict__ curB, uint2* __restrict__ pkB) {
    int i = blockIdx.x * blockDim.x + threadIdx.x;
    if (i >= 2 * NEDGE) return;
    if (i < NEDGE) {
        int e = i, d = dstA[e], s = srcA[e];
        int pos = atomicAdd(&curA[d], 1);
        pkA[pos] = make_uint2((uint32_t)s,
                              __float_as_uint(wA[e] * inv_sqrt_deg(degsA[s])));
    } else {
        int e = i - NEDGE, d = dstB[e], s = srcB[e];
        int pos = atomicAdd(&curB[d], 1);
        pkB[pos] = make_uint2((uint32_t)s,
                              __float_as_uint(wB[e] * inv_sqrt_deg(degsB[s])));
    }
}

// ---------------- gather (warp per node, x4 unrolled) -----------------------
template <int MODE>
__global__ void gather_kernel(__half* __restrict__ outh, const __half* __restrict__ h,
                              const uint2* __restrict__ packed,
                              const int* __restrict__ rowptr,
                              const float* __restrict__ deg_d,
                              const float* __restrict__ bias,
                              const float* __restrict__ Wc,
                              const int* __restrict__ batch,
                              float* __restrict__ psum, float* __restrict__ pcnt,
                              int n) {
    int node = blockIdx.x * (blockDim.x >> 5) + (threadIdx.x >> 5);
    if (node >= n) return;
    int lane = threadIdx.x & 31;
    int r0 = __ldg(rowptr + node), r1 = __ldg(rowptr + node + 1);
    float4 acc = make_float4(0.f, 0.f, 0.f, 0.f);
    for (int base = r0; base < r1; base += 32) {
        int nit = min(32, r1 - base);
        uint2 meta = (lane < nit) ? __ldg(packed + base + lane) : make_uint2(0u, 0u);
        int nit4 = (nit + 3) & ~3;
        for (int j = 0; j < nit4; j += 4) {
            int   s0 = __shfl_sync(0xffffffffu, (int)meta.x, j + 0);
            int   s1 = __shfl_sync(0xffffffffu, (int)meta.x, (j + 1) & 31);
            int   s2 = __shfl_sync(0xffffffffu, (int)meta.x, (j + 2) & 31);
            int   s3 = __shfl_sync(0xffffffffu, (int)meta.x, (j + 3) & 31);
            float w0 = __uint_as_float(__shfl_sync(0xffffffffu, meta.y, j + 0));
            float w1 = __uint_as_float(__shfl_sync(0xffffffffu, meta.y, (j + 1) & 31));
            float w2 = __uint_as_float(__shfl_sync(0xffffffffu, meta.y, (j + 2) & 31));
            float w3 = __uint_as_float(__shfl_sync(0xffffffffu, meta.y, (j + 3) & 31));
            uint2 v0 = *reinterpret_cast<const uint2*>(h + (size_t)s0 * 128 + lane * 4);
            uint2 v1 = *reinterpret_cast<const uint2*>(h + (size_t)s1 * 128 + lane * 4);
            uint2 v2 = *reinterpret_cast<const uint2*>(h + (size_t)s2 * 128 + lane * 4);
            uint2 v3 = *reinterpret_cast<const uint2*>(h + (size_t)s3 * 128 + lane * 4);
#define ACC(V, W)                                                              \
            {                                                                  \
                float2 fa = __half22float2(*reinterpret_cast<__half2*>(&V.x)); \
                float2 fb = __half22float2(*reinterpret_cast<__half2*>(&V.y)); \
                acc.x += (W) * fa.x; acc.y += (W) * fa.y;                      \
                acc.z += (W) * fb.x; acc.w += (W) * fb.y;                      \
            }
            ACC(v0, w0) ACC(v1, w1) ACC(v2, w2) ACC(v3, w3)
#undef ACC
        }
    }
    float dd = inv_sqrt_deg(__ldg(deg_d + node));
    acc.x *= dd; acc.y *= dd; acc.z *= dd; acc.w *= dd;
    float4 bb = reinterpret_cast<const float4*>(bias)[lane];
    acc.x = fmaxf(acc.x + bb.x, 0.f);
    acc.y = fmaxf(acc.y + bb.y, 0.f);
    acc.z = fmaxf(acc.z + bb.z, 0.f);
    acc.w = fmaxf(acc.w + bb.w, 0.f);
    if (MODE == 0) {
        __half2 o0 = __floats2half2_rn(acc.x, acc.y);
        __half2 o1 = __floats2half2_rn(acc.z, acc.w);
        *reinterpret_cast<uint2*>(outh + (size_t)node * 128 + lane * 4) =
            make_uint2(*reinterpret_cast<uint32_t*>(&o0), *reinterpret_cast<uint32_t*>(&o1));
    } else {
        float4 wc = reinterpret_cast<const float4*>(Wc)[lane];
        float s = acc.x * wc.x + acc.y * wc.y + acc.z * wc.z + acc.w * wc.w;
#pragma unroll
        for (int o = 16; o; o >>= 1) s += __shfl_down_sync(0xffffffffu, s, o);
        if (lane == 0) {
            int g = batch[node];
            atomicAdd(&psum[g], s);
            atomicAdd(&pcnt[g], 1.f);
        }
    }
}

// ---------------- shared MMA compute (ldmatrix fragments) -------------------
#define MMA_TILE_COMPUTE(as, bs)                                               \
    do {                                                                       \
        _Pragma("unroll")                                                      \
        for (int kk = 0; kk < 32; kk += 16) {                                  \
            uint32_t afr[2][4], bfr[8][2];                                     \
            _Pragma("unroll")                                                  \
            for (int mi = 0; mi < 2; mi++)                                     \
                ldsm_x4(afr[mi][0], afr[mi][1], afr[mi][2], afr[mi][3],        \
                        &(as)[(wm + mi * 16 + lrow) * PITCH + kk + lcol]);     \
            _Pragma("unroll")                                                  \
            for (int nb = 0; nb < 4; nb++) {                                   \
                uint32_t q0, q1, q2, q3;                                       \
                ldsm_x4(q0, q1, q2, q3,                                        \
                        &(bs)[(wn + nb * 16 + lrow) * PITCH + kk + lcol]);     \
                bfr[2 * nb][0] = q0; bfr[2 * nb + 1][0] = q1;                  \
                bfr[2 * nb][1] = q2; bfr[2 * nb + 1][1] = q3;                  \
            }                                                                  \
            _Pragma("unroll")                                                  \
            for (int mi = 0; mi < 2; mi++)                                     \
                _Pragma("unroll")                                              \
                for (int ni = 0; ni < 8; ni++)                                 \
                    mma_f16(acc[mi][ni], afr[mi], bfr[ni]);                    \
        }                                                                      \
    } while (0)

#define MMA_EPILOGUE(C, M)                                                     \
    do {                                                                       \
        _Pragma("unroll")                                                      \
        for (int mi = 0; mi < 2; mi++)                                         \
            _Pragma("unroll")                                                  \
            for (int ni = 0; ni < 8; ni++) {                                   \
                int r1 = row0 + wm + mi * 16 + gid;                            \
                int r2 = r1 + 8;                                               \
                int c  = wn + ni * 8 + tid4 * 2;                               \
                if (r1 < (M))                                                  \
                    *reinterpret_cast<__half2*>((C) + (size_t)r1 * 128 + c) =  \
                        __floats2half2_rn(acc[mi][ni][0], acc[mi][ni][1]);     \
                if (r2 < (M))                                                  \
                    *reinterpret_cast<__half2*>((C) + (size_t)r2 * 128 + c) =  \
                        __floats2half2_rn(acc[mi][ni][2], acc[mi][ni][3]);     \
            }                                                                  \
    } while (0)

// ---------------- GEMM1: A f32 -> cvt in reg -> STS; B fp16 cp.async --------
// R7-proven structure: static shared, 2-stage both operands, two syncs/tile.
__global__ __launch_bounds__(256) void hgemm1_kernel(
        const float* __restrict__ A, const __half* __restrict__ Bt,
        __half* __restrict__ C, int M, int K) {
    __shared__ __half Asm[2][STGH];
    __shared__ __half Bsm[2][STGH];

    const int tid  = threadIdx.x;
    const int wid  = tid >> 5;
    const int lane = tid & 31;
    const int gid  = lane >> 2;
    const int tid4 = lane & 3;
    const int wm   = (wid & 3) * 32;
    const int wn   = (wid >> 2) * 64;
    const int row0 = blockIdx.x * 128;
    const int nt   = K >> 5;
    const int lrow = ((lane >> 3) & 1) * 8 + (lane & 7);   // ldmatrix row offset
    const int lcol = (lane >> 4) * 8;                      // ldmatrix col offset

    float acc[2][8][4] = {};
    int aR[4]; const int aC = (tid & 7) * 4;
    int bR[2]; const int bK = (tid & 3) * 8;
#pragma unroll
    for (int i = 0; i < 4; i++) aR[i] = (tid + i * 256) >> 3;
#pragma unroll
    for (int i = 0; i < 2; i++) bR[i] = (tid + i * 256) >> 2;

    float4 av[4];
#define G_LDG(t)                                                               \
    do {                                                                       \
        int k0 = (t) * 32;                                                     \
        _Pragma("unroll")                                                      \
        for (int i = 0; i < 4; i++) {                                          \
            int r = row0 + aR[i];                                              \
            av[i] = (r < M) ? *reinterpret_cast<const float4*>(                \
                                  A + (size_t)r * K + k0 + aC)                 \
                            : make_float4(0.f, 0.f, 0.f, 0.f);                 \
        }                                                                      \
    } while (0)
#define G_CPB(t)                                                               \
    do {                                                                       \
        int k0 = (t) * 32;                                                     \
        _Pragma("unroll")                                                      \
        for (int i = 0; i < 2; i++)                                            \
            cpa16(&Bsm[(t) & 1][bR[i] * PITCH + bK],                           \
                  Bt + (size_t)bR[i] * K + k0 + bK);                           \
    } while (0)
#define G_STS(t)                                                               \
    do {                                                                       \
        _Pragma("unroll")                                                      \
        for (int i = 0; i < 4; i++) {                                          \
            __half2 h0 = __floats2half2_rn(av[i].x, av[i].y);                  \
            __half2 h1 = __floats2half2_rn(av[i].z, av[i].w);                  \
            *reinterpret_cast<uint2*>(&Asm[(t) & 1][aR[i] * PITCH + aC]) =     \
                make_uint2(*reinterpret_cast<uint32_t*>(&h0),                  \
                           *reinterpret_cast<uint32_t*>(&h1));                 \
        }                                                                      \
    } while (0)

    G_LDG(0);
    G_CPB(0); CP_COMMIT();

    for (int t = 0; t < nt; t++) {
        G_STS(t);
        if (t + 1 < nt) { G_LDG(t + 1); G_CPB(t + 1); }
        CP_COMMIT();
        CP_WAIT1();
        __syncthreads();
        MMA_TILE_COMPUTE(Asm[t & 1], Bsm[t & 1]);
        __syncthreads();
    }

    MMA_EPILOGUE(C, M);
#undef G_LDG
#undef G_CPB
#undef G_STS
}

// ---------------- GEMM2: both operands fp16 via cp.async --------------------
__global__ __launch_bounds__(256) void hgemm2_kernel(
        const __half* __restrict__ A, const __half* __restrict__ Bt,
        __half* __restrict__ C, int M, int K) {
    __shared__ __half Asm[2][STGH];
    __shared__ __half Bsm[2][STGH];

    const int tid  = threadIdx.x;
    const int wid  = tid >> 5;
    const int lane = tid & 31;
    const int gid  = lane >> 2;
    const int tid4 = lane & 3;
    const int wm   = (wid & 3) * 32;
    const int wn   = (wid >> 2) * 64;
    const int row0 = blockIdx.x * 128;
    const int nt   = K >> 5;
    const int lrow = ((lane >> 3) & 1) * 8 + (lane & 7);
    const int lcol = (lane >> 4) * 8;

    float acc[2][8][4] = {};
    int xR[2]; const int xK = (tid & 3) * 8;
#pragma unroll
    for (int i = 0; i < 2; i++) xR[i] = (tid + i * 256) >> 2;

#define G2_CP(t)                                                               \
    do {                                                                       \
        int k0 = (t) * 32;                                                     \
        _Pragma("unroll")                                                      \
        for (int i = 0; i < 2; i++) {                                          \
            int r = row0 + xR[i];                                              \
            const __half* gp = (r < M) ? A + (size_t)r * K + k0 + xK           \
                                       : A + k0 + xK;                          \
            cpa16(&Asm[(t) & 1][xR[i] * PITCH + xK], gp);                      \
            cpa16(&Bsm[(t) & 1][xR[i] * PITCH + xK],                           \
                  Bt + (size_t)xR[i] * K + k0 + xK);                           \
        }                                                                      \
    } while (0)

    G2_CP(0); CP_COMMIT();

    for (int t = 0; t < nt; t++) {
        if (t + 1 < nt) G2_CP(t + 1);
        CP_COMMIT();
        CP_WAIT1();
        __syncthreads();
        MMA_TILE_COMPUTE(Asm[t & 1], Bsm[t & 1]);
        __syncthreads();
    }

    MMA_EPILOGUE(C, M);
#undef G2_CP
}

__global__ void final_kernel(const float* __restrict__ psum,
                             const float* __restrict__ pcnt,
                             const float* __restrict__ bc,
                             float* __restrict__ out) {
    int g = threadIdx.x;
    if (g < NB) out[g] = psum[g] / fmaxf(pcnt[g], 1.f) + bc[0];
}

// ---------------- launch ---------------------------------------------------
extern "C" void kernel_launch(void* const* d_in, const int* in_sizes, int n_in,
                              void* d_out, int out_size) {
    const float* x_fact     = (const float*)d_in[0];
    const float* ea_fc      = (const float*)d_in[2];
    const float* ea_cf      = (const float*)d_in[3];
    const int*   fc_src     = (const int*)d_in[4];
    const int*   fc_dst     = (const int*)d_in[5];
    const int*   cf_src     = (const int*)d_in[6];
    const int*   cf_dst     = (const int*)d_in[7];
    const int*   batch_fact = (const int*)d_in[8];
    const float* Wm         = (const float*)d_in[9];
    const float* bm         = (const float*)d_in[10];
    const float* W1_fc      = (const float*)d_in[11];
    const float* b1_fc      = (const float*)d_in[12];
    const float* W2_cf      = (const float*)d_in[17];
    const float* b2_cf      = (const float*)d_in[18];
    const float* Wc         = (const float*)d_in[19];
    const float* bc         = (const float*)d_in[20];
    float* out = (float*)d_out;

    float *wfc, *wcf, *dfcs, *dfcd, *dcfs, *dcfd, *psum, *pcnt;
    __half *W1t, *W2t, *H1, *c1h, *H2;
    int *cntc, *cntf, *bsum, *rpc, *rpf, *curc, *curf;
    uint2 *pfc, *pcf;
    cudaGetSymbolAddress((void**)&wfc,  g_wfc);
    cudaGetSymbolAddress((void**)&wcf,  g_wcf);
    cudaGetSymbolAddress((void**)&dfcs, g_dfc_s);
    cudaGetSymbolAddress((void**)&dfcd, g_dfc_d);
    cudaGetSymbolAddress((void**)&dcfs, g_dcf_s);
    cudaGetSymbolAddress((void**)&dcfd, g_dcf_d);
    cudaGetSymbolAddress((void**)&W1t,  g_W1t);
    cudaGetSymbolAddress((void**)&W2t,  g_W2t);
    cudaGetSymbolAddress((void**)&H1,   g_H1);
    cudaGetSymbolAddress((void**)&c1h,  g_c1h);
    cudaGetSymbolAddress((void**)&H2,   g_H2);
    cudaGetSymbolAddress((void**)&psum, g_psum);
    cudaGetSymbolAddress((void**)&pcnt, g_pcnt);
    cudaGetSymbolAddress((void**)&cntc, g_cntc);
    cudaGetSymbolAddress((void**)&cntf, g_cntf);
    cudaGetSymbolAddress((void**)&bsum, g_bsum);
    cudaGetSymbolAddress((void**)&rpc,  g_rpc);
    cudaGetSymbolAddress((void**)&rpf,  g_rpf);
    cudaGetSymbolAddress((void**)&curc, g_curc);
    cudaGetSymbolAddress((void**)&curf, g_curf);
    cudaGetSymbolAddress((void**)&pfc,  g_pfc);
    cudaGetSymbolAddress((void**)&pcf,  g_pcf);

    cudaMemsetAsync(dfcs, 0, NFACT * sizeof(float));
    cudaMemsetAsync(dfcd, 0, NCOMP * sizeof(float));
    cudaMemsetAsync(dcfs, 0, NCOMP * sizeof(float));
    cudaMemsetAsync(dcfd, 0, NFACT * sizeof(float));
    cudaMemsetAsync(cntc, 0, NCOMP * sizeof(int));
    cudaMemsetAsync(cntf, 0, NFACT * sizeof(int));
    cudaMemsetAsync(psum, 0, NB * sizeof(float));
    cudaMemsetAsync(pcnt, 0, NB * sizeof(float));

    const int nbC = (NCOMP + SCAN_BS - 1) / SCAN_BS;   // 40
    const int nbF = (NFACT + SCAN_BS - 1) / SCAN_BS;   // 391

    // 1: gates + degrees + histograms, both relations
    gate_deg2_kernel<<<(2 * NEDGE + 255) / 256, 256>>>(
        ea_fc, ea_cf, fc_src, fc_dst, cf_src, cf_dst, Wm, bm,
        wfc, wcf, dfcs, dfcd, dcfs, dcfd, cntc, cntf);
    // 2: weights transpose + fp16 round
    prep_w_kernel<<<(DFACT * HID + HID * HID + 255) / 256, 256>>>(W1_fc, W2_cf, W1t, W2t);
    // 3: block sums for both scans
    scan_bsum2_kernel<<<nbC + nbF, SCAN_BS>>>(cntc, cntf, nbC, bsum);
    // 4: GEMM1 (profiled slot)
    hgemm1_kernel<<<(NFACT + 127) / 128, 256>>>(x_fact, W1t, H1, NFACT, DFACT);
    // 5-6: finish scans
    scan_tops2_kernel<<<2, 1024>>>(bsum, nbC, nbF, rpc, rpf);
    scan_write2_kernel<<<nbC + nbF, SCAN_BS>>>(cntc, cntf, bsum, nbC,
                                               rpc, curc, rpf, curf);
    // 7: scatter both relations
    scatter2_kernel<<<(2 * NEDGE + 255) / 256, 256>>>(
        fc_src, fc_dst, wfc, dfcs, curc, pfc,
        cf_src, cf_dst, wcf, dcfs, curf, pcf);
    // 8: gather1 -> c1h = fp16(relu(agg + b1))
    gather_kernel<0><<<(NCOMP + 7) / 8, 256>>>(c1h, H1, pfc, rpc, dfcd,
                                               b1_fc, nullptr, nullptr,
                                               nullptr, nullptr, NCOMP);
    // 9: GEMM2 (pure fp16)
    hgemm2_kernel<<<(NCOMP + 127) / 128, 256>>>(c1h, W2t, H2, NCOMP, HID);
    // 10: gather2 + relu + classifier dot + pool (fused)
    gather_kernel<1><<<(NFACT + 7) / 8, 256>>>(nullptr, H2, pcf, rpf, dcfd,
                                               b2_cf, Wc, batch_fact,
                                               psum, pcnt, NFACT);
    // 11: final
    final_kernel<<<1, NB>>>(psum, pcnt, bc, out);
}

// round 14
// speedup vs baseline: 1.3652x; 1.0880x over previous
#include <cuda_runtime.h>
#include <cuda_fp16.h>
#include <cstdint>

#define NFACT 100000
#define NCOMP 10000
#define NEDGE 800000
#define DFACT 768
#define HID   128
#define NB    256

#define PITCH 40                 // halves per smem row; 80B stride -> ldmatrix conflict-free
#define STGH  (128 * PITCH)      // halves per stage
#define SCAN_BS 256
#define FOFF 512                 // bsum offset for fact-relation blocks

// ---------------- scratch (device globals; no allocation allowed) ----------
__device__ float g_wfc[NEDGE];
__device__ float g_wcf[NEDGE];
__device__ float g_dfc_s[NFACT];
__device__ float g_dfc_d[NCOMP];
__device__ float g_dcf_s[NCOMP];
__device__ float g_dcf_d[NFACT];
__device__ __align__(16) __half g_W1t[(size_t)HID * DFACT];  // [n][k] fp16
__device__ __align__(16) __half g_W2t[(size_t)HID * HID];    // [n][k] fp16
__device__ __align__(16) __half g_H1[(size_t)NFACT * HID];
__device__ __align__(16) __half g_c1h[(size_t)NCOMP * HID];  // relu(agg+b1) fp16
__device__ __align__(16) __half g_H2[(size_t)NCOMP * HID];
__device__ float g_psum[NB];
__device__ float g_pcnt[NB];
// CSR scratch
__device__ int   g_cntc[NCOMP];
__device__ int   g_cntf[NFACT];
__device__ int   g_bsum[1024];
__device__ int   g_rpc[NCOMP + 1];
__device__ int   g_rpf[NFACT + 1];
__device__ int   g_curc[NCOMP];
__device__ int   g_curf[NFACT];
__device__ uint2 g_pfc[NEDGE];
__device__ uint2 g_pcf[NEDGE];

// ---------------- helpers --------------------------------------------------
__device__ __forceinline__ void mma_f16(float* c, const uint32_t* a, const uint32_t* b) {
    asm volatile(
        "mma.sync.aligned.m16n8k16.row.col.f32.f16.f16.f32 "
        "{%0,%1,%2,%3}, {%4,%5,%6,%7}, {%8,%9}, {%0,%1,%2,%3};"
        : "+f"(c[0]), "+f"(c[1]), "+f"(c[2]), "+f"(c[3])
        : "r"(a[0]), "r"(a[1]), "r"(a[2]), "r"(a[3]), "r"(b[0]), "r"(b[1]));
}
__device__ __forceinline__ void ldsm_x4(uint32_t& r0, uint32_t& r1, uint32_t& r2,
                                        uint32_t& r3, const __half* p) {
    uint32_t a = (uint32_t)__cvta_generic_to_shared(p);
    asm volatile("ldmatrix.sync.aligned.m8n8.x4.shared.b16 {%0,%1,%2,%3}, [%4];"
                 : "=r"(r0), "=r"(r1), "=r"(r2), "=r"(r3) : "r"(a));
}
#define CP_COMMIT() asm volatile("cp.async.commit_group;")
#define CP_WAIT1()  asm volatile("cp.async.wait_group 1;")
__device__ __forceinline__ void cpa16(__half* sp, const __half* gp) {
    uint32_t sa = (uint32_t)__cvta_generic_to_shared(sp);
    asm volatile("cp.async.cg.shared.global [%0], [%1], 16;" :: "r"(sa), "l"(gp));
}
__device__ __forceinline__ float inv_sqrt_deg(float d) {
    return (d > 0.f) ? rsqrtf(d) : 0.f;
}

// ---------------- fused edge kernels ---------------------------------------
__global__ void gate_deg2_kernel(const float* __restrict__ eaA, const float* __restrict__ eaB,
                                 const int* __restrict__ srcA, const int* __restrict__ dstA,
                                 const int* __restrict__ srcB, const int* __restrict__ dstB,
                                 const float* __restrict__ Wm, const float* __restrict__ bm,
                                 float* __restrict__ wA, float* __restrict__ wB,
                                 float* __restrict__ degsA, float* __restrict__ degdA,
                                 float* __restrict__ degsB, float* __restrict__ degdB,
                                 int* __restrict__ cntA, int* __restrict__ cntB) {
    int i = blockIdx.x * blockDim.x + threadIdx.x;
    int e = (i < NEDGE) ? i : i - NEDGE;
    if (i >= 2 * NEDGE) return;
    const float* ea = (i < NEDGE) ? eaA : eaB;
    float a0 = ea[2 * e + 0], a1 = ea[2 * e + 1];
    float z  = a0 * Wm[0] + a1 * Wm[1] + bm[0];
    float ww = 1.f / (1.f + expf(-z));
    if (i < NEDGE) {
        wA[e] = ww;
        int d = dstA[e];
        atomicAdd(&degsA[srcA[e]], ww);
        atomicAdd(&degdA[d], ww);
        atomicAdd(&cntA[d], 1);
    } else {
        wB[e] = ww;
        int d = dstB[e];
        atomicAdd(&degsB[srcB[e]], ww);
        atomicAdd(&degdB[d], ww);
        atomicAdd(&cntB[d], 1);
    }
}

__global__ void prep_w_kernel(const float* __restrict__ W1, const float* __restrict__ W2,
                              __half* __restrict__ W1t, __half* __restrict__ W2t) {
    int i = blockIdx.x * blockDim.x + threadIdx.x;
    int n1 = DFACT * HID;
    if (i < n1) {
        int k = i >> 7, n = i & 127;
        W1t[(size_t)n * DFACT + k] = __float2half_rn(W1[i]);
    } else if (i < n1 + HID * HID) {
        int j = i - n1;
        int k = j >> 7, n = j & 127;
        W2t[(size_t)n * HID + k] = __float2half_rn(W2[j]);
    }
}

// ---------------- CSR build (merged grids) ----------------------------------
__global__ void scan_bsum2_kernel(const int* __restrict__ cntc, const int* __restrict__ cntf,
                                  int nbC, int* __restrict__ bsum) {
    __shared__ int sh[SCAN_BS];
    bool isC = (int)blockIdx.x < nbC;
    const int* cnt = isC ? cntc : cntf;
    int n   = isC ? NCOMP : NFACT;
    int bid = isC ? blockIdx.x : blockIdx.x - nbC;
    int i = bid * SCAN_BS + threadIdx.x;
    sh[threadIdx.x] = (i < n) ? cnt[i] : 0;
    __syncthreads();
    for (int o = SCAN_BS / 2; o; o >>= 1) {
        if (threadIdx.x < o) sh[threadIdx.x] += sh[threadIdx.x + o];
        __syncthreads();
    }
    if (threadIdx.x == 0) bsum[(isC ? 0 : FOFF) + bid] = sh[0];
}

__global__ void scan_tops2_kernel(int* __restrict__ bsum, int nbC, int nbF,
                                  int* __restrict__ rpc, int* __restrict__ rpf) {
    __shared__ int sh[1024];
    bool isC = (blockIdx.x == 0);
    int* bs = bsum + (isC ? 0 : FOFF);
    int nb  = isC ? nbC : nbF;
    int tid = threadIdx.x;
    int v = (tid < nb) ? bs[tid] : 0;
    sh[tid] = v;
    __syncthreads();
    for (int o = 1; o < 1024; o <<= 1) {
        int t = (tid >= o) ? sh[tid - o] : 0;
        __syncthreads();
        sh[tid] += t;
        __syncthreads();
    }
    if (tid < nb) bs[tid] = sh[tid] - v;
    if (tid == 0) { if (isC) rpc[NCOMP] = sh[1023]; else rpf[NFACT] = sh[1023]; }
}

__global__ void scan_write2_kernel(const int* __restrict__ cntc, const int* __restrict__ cntf,
                                   const int* __restrict__ bsum, int nbC,
                                   int* __restrict__ rpc, int* __restrict__ curc,
                                   int* __restrict__ rpf, int* __restrict__ curf) {
    __shared__ int sh[SCAN_BS];
    bool isC = (int)blockIdx.x < nbC;
    const int* cnt = isC ? cntc : cntf;
    int n   = isC ? NCOMP : NFACT;
    int bid = isC ? blockIdx.x : blockIdx.x - nbC;
    int* rowptr = isC ? rpc : rpf;
    int* cur    = isC ? curc : curf;
    int bofs = (isC ? 0 : FOFF) + bid;
    int tid = threadIdx.x;
    int i = bid * SCAN_BS + tid;
    int v = (i < n) ? cnt[i] : 0;
    sh[tid] = v;
    __syncthreads();
    for (int o = 1; o < SCAN_BS; o <<= 1) {
        int t = (tid >= o) ? sh[tid - o] : 0;
        __syncthreads();
        sh[tid] += t;
        __syncthreads();
    }
    if (i < n) {
        int ex = sh[tid] - v + bsum[bofs];
        rowptr[i] = ex;
        cur[i] = ex;
    }
}

__global__ void scatter2_kernel(const int* __restrict__ srcA, const int* __restrict__ dstA,
                                const float* __restrict__ wA, const float* __restrict__ degsA,
                                int* __restrict__ curA, uint2* __restrict__ pkA,
                                const int* __restrict__ srcB, const int* __restrict__ dstB,
                                const float* __restrict__ wB, const float* __restrict__ degsB,
                                int* __restrict__ curB, uint2* __restrict__ pkB) {
    int i = blockIdx.x * blockDim.x + threadIdx.x;
    if (i >= 2 * NEDGE) return;
    if (i < NEDGE) {
        int e = i, d = dstA[e], s = srcA[e];
        int pos = atomicAdd(&curA[d], 1);
        pkA[pos] = make_uint2((uint32_t)s,
                              __float_as_uint(wA[e] * inv_sqrt_deg(degsA[s])));
    } else {
        int e = i - NEDGE, d = dstB[e], s = srcB[e];
        int pos = atomicAdd(&curB[d], 1);
        pkB[pos] = make_uint2((uint32_t)s,
                              __float_as_uint(wB[e] * inv_sqrt_deg(degsB[s])));
    }
}

// ---------------- gather (warp per node, x4 unrolled) -----------------------
template <int MODE>
__global__ void gather_kernel(__half* __restrict__ outh, const __half* __restrict__ h,
                              const uint2* __restrict__ packed,
                              const int* __restrict__ rowptr,
                              const float* __restrict__ deg_d,
                              const float* __restrict__ bias,
                              const float* __restrict__ Wc,
                              const int* __restrict__ batch,
                              float* __restrict__ psum, float* __restrict__ pcnt,
                              int n) {
    int node = blockIdx.x * (blockDim.x >> 5) + (threadIdx.x >> 5);
    if (node >= n) return;
    int lane = threadIdx.x & 31;
    int r0 = __ldg(rowptr + node), r1 = __ldg(rowptr + node + 1);
    float4 acc = make_float4(0.f, 0.f, 0.f, 0.f);
    for (int base = r0; base < r1; base += 32) {
        int nit = min(32, r1 - base);
        uint2 meta = (lane < nit) ? __ldg(packed + base + lane) : make_uint2(0u, 0u);
        int nit4 = (nit + 3) & ~3;
        for (int j = 0; j < nit4; j += 4) {
            int   s0 = __shfl_sync(0xffffffffu, (int)meta.x, j + 0);
            int   s1 = __shfl_sync(0xffffffffu, (int)meta.x, (j + 1) & 31);
            int   s2 = __shfl_sync(0xffffffffu, (int)meta.x, (j + 2) & 31);
            int   s3 = __shfl_sync(0xffffffffu, (int)meta.x, (j + 3) & 31);
            float w0 = __uint_as_float(__shfl_sync(0xffffffffu, meta.y, j + 0));
            float w1 = __uint_as_float(__shfl_sync(0xffffffffu, meta.y, (j + 1) & 31));
            float w2 = __uint_as_float(__shfl_sync(0xffffffffu, meta.y, (j + 2) & 31));
            float w3 = __uint_as_float(__shfl_sync(0xffffffffu, meta.y, (j + 3) & 31));
            uint2 v0 = *reinterpret_cast<const uint2*>(h + (size_t)s0 * 128 + lane * 4);
            uint2 v1 = *reinterpret_cast<const uint2*>(h + (size_t)s1 * 128 + lane * 4);
            uint2 v2 = *reinterpret_cast<const uint2*>(h + (size_t)s2 * 128 + lane * 4);
            uint2 v3 = *reinterpret_cast<const uint2*>(h + (size_t)s3 * 128 + lane * 4);
#define ACC(V, W)                                                              \
            {                                                                  \
                float2 fa = __half22float2(*reinterpret_cast<__half2*>(&V.x)); \
                float2 fb = __half22float2(*reinterpret_cast<__half2*>(&V.y)); \
                acc.x += (W) * fa.x; acc.y += (W) * fa.y;                      \
                acc.z += (W) * fb.x; acc.w += (W) * fb.y;                      \
            }
            ACC(v0, w0) ACC(v1, w1) ACC(v2, w2) ACC(v3, w3)
#undef ACC
        }
    }
    float dd = inv_sqrt_deg(__ldg(deg_d + node));
    acc.x *= dd; acc.y *= dd; acc.z *= dd; acc.w *= dd;
    float4 bb = reinterpret_cast<const float4*>(bias)[lane];
    acc.x = fmaxf(acc.x + bb.x, 0.f);
    acc.y = fmaxf(acc.y + bb.y, 0.f);
    acc.z = fmaxf(acc.z + bb.z, 0.f);
    acc.w = fmaxf(acc.w + bb.w, 0.f);
    if (MODE == 0) {
        __half2 o0 = __floats2half2_rn(acc.x, acc.y);
        __half2 o1 = __floats2half2_rn(acc.z, acc.w);
        *reinterpret_cast<uint2*>(outh + (size_t)node * 128 + lane * 4) =
            make_uint2(*reinterpret_cast<uint32_t*>(&o0), *reinterpret_cast<uint32_t*>(&o1));
    } else {
        float4 wc = reinterpret_cast<const float4*>(Wc)[lane];
        float s = acc.x * wc.x + acc.y * wc.y + acc.z * wc.z + acc.w * wc.w;
#pragma unroll
        for (int o = 16; o; o >>= 1) s += __shfl_down_sync(0xffffffffu, s, o);
        if (lane == 0) {
            int g = batch[node];
            atomicAdd(&psum[g], s);
            atomicAdd(&pcnt[g], 1.f);
        }
    }
}

// ---------------- shared MMA compute (ldmatrix fragments) -------------------
#define MMA_TILE_COMPUTE(as, bs)                                               \
    do {                                                                       \
        _Pragma("unroll")                                                      \
        for (int kk = 0; kk < 32; kk += 16) {                                  \
            uint32_t afr[2][4], bfr[8][2];                                     \
            _Pragma("unroll")                                                  \
            for (int mi = 0; mi < 2; mi++)                                     \
                ldsm_x4(afr[mi][0], afr[mi][1], afr[mi][2], afr[mi][3],        \
                        &(as)[(wm + mi * 16 + lrow) * PITCH + kk + lcol]);     \
            _Pragma("unroll")                                                  \
            for (int nb = 0; nb < 4; nb++) {                                   \
                uint32_t q0, q1, q2, q3;                                       \
                ldsm_x4(q0, q1, q2, q3,                                        \
                        &(bs)[(wn + nb * 16 + lrow) * PITCH + kk + lcol]);     \
                bfr[2 * nb][0] = q0; bfr[2 * nb + 1][0] = q1;                  \
                bfr[2 * nb][1] = q2; bfr[2 * nb + 1][1] = q3;                  \
            }                                                                  \
            _Pragma("unroll")                                                  \
            for (int mi = 0; mi < 2; mi++)                                     \
                _Pragma("unroll")                                              \
                for (int ni = 0; ni < 8; ni++)                                 \
                    mma_f16(acc[mi][ni], afr[mi], bfr[ni]);                    \
        }                                                                      \
    } while (0)

#define MMA_EPILOGUE(C, M)                                                     \
    do {                                                                       \
        _Pragma("unroll")                                                      \
        for (int mi = 0; mi < 2; mi++)                                         \
            _Pragma("unroll")                                                  \
            for (int ni = 0; ni < 8; ni++) {                                   \
                int r1 = row0 + wm + mi * 16 + gid;                            \
                int r2 = r1 + 8;                                               \
                int c  = wn + ni * 8 + tid4 * 2;                               \
                if (r1 < (M))                                                  \
                    *reinterpret_cast<__half2*>((C) + (size_t)r1 * 128 + c) =  \
                        __floats2half2_rn(acc[mi][ni][0], acc[mi][ni][1]);     \
                if (r2 < (M))                                                  \
                    *reinterpret_cast<__half2*>((C) + (size_t)r2 * 128 + c) =  \
                        __floats2half2_rn(acc[mi][ni][2], acc[mi][ni][3]);     \
            }                                                                  \
    } while (0)

// ---------------- GEMM1: A f32 -> cvt in reg -> STS; B fp16 cp.async --------
__global__ __launch_bounds__(256) void hgemm1_kernel(
        const float* __restrict__ A, const __half* __restrict__ Bt,
        __half* __restrict__ C, int M, int K) {
    __shared__ __half Asm[2][STGH];
    __shared__ __half Bsm[2][STGH];

    const int tid  = threadIdx.x;
    const int wid  = tid >> 5;
    const int lane = tid & 31;
    const int gid  = lane >> 2;
    const int tid4 = lane & 3;
    const int wm   = (wid & 3) * 32;
    const int wn   = (wid >> 2) * 64;
    const int row0 = blockIdx.x * 128;
    const int nt   = K >> 5;
    const int lrow = ((lane >> 3) & 1) * 8 + (lane & 7);   // ldmatrix row offset
    const int lcol = (lane >> 4) * 8;                      // ldmatrix col offset

    float acc[2][8][4] = {};
    int aR[4]; const int aC = (tid & 7) * 4;
    int bR[2]; const int bK = (tid & 3) * 8;
#pragma unroll
    for (int i = 0; i < 4; i++) aR[i] = (tid + i * 256) >> 3;
#pragma unroll
    for (int i = 0; i < 2; i++) bR[i] = (tid + i * 256) >> 2;

    float4 av[4];
#define G_LDG(t)                                                               \
    do {                                                                       \
        int k0 = (t) * 32;                                                     \
        _Pragma("unroll")                                                      \
        for (int i = 0; i < 4; i++) {                                          \
            int r = row0 + aR[i];                                              \
            av[i] = (r < M) ? *reinterpret_cast<const float4*>(                \
                                  A + (size_t)r * K + k0 + aC)                 \
                            : make_float4(0.f, 0.f, 0.f, 0.f);                 \
        }                                                                      \
    } while (0)
#define G_CPB(t)                                                               \
    do {                                                                       \
        int k0 = (t) * 32;                                                     \
        _Pragma("unroll")                                                      \
        for (int i = 0; i < 2; i++)                                            \
            cpa16(&Bsm[(t) & 1][bR[i] * PITCH + bK],                           \
                  Bt + (size_t)bR[i] * K + k0 + bK);                           \
    } while (0)
#define G_STS(t)                                                               \
    do {                                                                       \
        _Pragma("unroll")                                                      \
        for (int i = 0; i < 4; i++) {                                          \
            __half2 h0 = __floats2half2_rn(av[i].x, av[i].y);                  \
            __half2 h1 = __floats2half2_rn(av[i].z, av[i].w);                  \
            *reinterpret_cast<uint2*>(&Asm[(t) & 1][aR[i] * PITCH + aC]) =     \
                make_uint2(*reinterpret_cast<uint32_t*>(&h0),                  \
                           *reinterpret_cast<uint32_t*>(&h1));                 \
        }                                                                      \
    } while (0)

    G_LDG(0);
    G_CPB(0); CP_COMMIT();

    for (int t = 0; t < nt; t++) {
        G_STS(t);
        if (t + 1 < nt) { G_LDG(t + 1); G_CPB(t + 1); }
        CP_COMMIT();
        CP_WAIT1();
        __syncthreads();
        MMA_TILE_COMPUTE(Asm[t & 1], Bsm[t & 1]);
        __syncthreads();
    }

    MMA_EPILOGUE(C, M);
#undef G_LDG
#undef G_CPB
#undef G_STS
}

// ---------------- GEMM2: both operands fp16 via cp.async --------------------
__global__ __launch_bounds__(256) void hgemm2_kernel(
        const __half* __restrict__ A, const __half* __restrict__ Bt,
        __half* __restrict__ C, int M, int K) {
    __shared__ __half Asm[2][STGH];
    __shared__ __half Bsm[2][STGH];

    const int tid  = threadIdx.x;
    const int wid  = tid >> 5;
    const int lane = tid & 31;
    const int gid  = lane >> 2;
    const int tid4 = lane & 3;
    const int wm   = (wid & 3) * 32;
    const int wn   = (wid >> 2) * 64;
    const int row0 = blockIdx.x * 128;
    const int nt   = K >> 5;
    const int lrow = ((lane >> 3) & 1) * 8 + (lane & 7);
    const int lcol = (lane >> 4) * 8;

    float acc[2][8][4] = {};
    int xR[2]; const int xK = (tid & 3) * 8;
#pragma unroll
    for (int i = 0; i < 2; i++) xR[i] = (tid + i * 256) >> 2;

#define G2_CP(t)                                                               \
    do {                                                                       \
        int k0 = (t) * 32;                                                     \
        _Pragma("unroll")                                                      \
        for (int i = 0; i < 2; i++) {                                          \
            int r = row0 + xR[i];                                              \
            const __half* gp = (r < M) ? A + (size_t)r * K + k0 + xK           \
                                       : A + k0 + xK;                          \
            cpa16(&Asm[(t) & 1][xR[i] * PITCH + xK], gp);                      \
            cpa16(&Bsm[(t) & 1][xR[i] * PITCH + xK],                           \
                  Bt + (size_t)xR[i] * K + k0 + xK);                           \
        }                                                                      \
    } while (0)

    G2_CP(0); CP_COMMIT();

    for (int t = 0; t < nt; t++) {
        if (t + 1 < nt) G2_CP(t + 1);
        CP_COMMIT();
        CP_WAIT1();
        __syncthreads();
        MMA_TILE_COMPUTE(Asm[t & 1], Bsm[t & 1]);
        __syncthreads();
    }

    MMA_EPILOGUE(C, M);
#undef G2_CP
}

__global__ void final_kernel(const float* __restrict__ psum,
                             const float* __restrict__ pcnt,
                             const float* __restrict__ bc,
                             float* __restrict__ out) {
    int g = threadIdx.x;
    if (g < NB) out[g] = psum[g] / fmaxf(pcnt[g], 1.f) + bc[0];
}

// ---------------- launch ---------------------------------------------------
extern "C" void kernel_launch(void* const* d_in, const int* in_sizes, int n_in,
                              void* d_out, int out_size) {
    const float* x_fact     = (const float*)d_in[0];
    const float* ea_fc      = (const float*)d_in[2];
    const float* ea_cf      = (const float*)d_in[3];
    const int*   fc_src     = (const int*)d_in[4];
    const int*   fc_dst     = (const int*)d_in[5];
    const int*   cf_src     = (const int*)d_in[6];
    const int*   cf_dst     = (const int*)d_in[7];
    const int*   batch_fact = (const int*)d_in[8];
    const float* Wm         = (const float*)d_in[9];
    const float* bm         = (const float*)d_in[10];
    const float* W1_fc      = (const float*)d_in[11];
    const float* b1_fc      = (const float*)d_in[12];
    const float* W2_cf      = (const float*)d_in[17];
    const float* b2_cf      = (const float*)d_in[18];
    const float* Wc         = (const float*)d_in[19];
    const float* bc         = (const float*)d_in[20];
    float* out = (float*)d_out;

    float *wfc, *wcf, *dfcs, *dfcd, *dcfs, *dcfd, *psum, *pcnt;
    __half *W1t, *W2t, *H1, *c1h, *H2;
    int *cntc, *cntf, *bsum, *rpc, *rpf, *curc, *curf;
    uint2 *pfc, *pcf;
    cudaGetSymbolAddress((void**)&wfc,  g_wfc);
    cudaGetSymbolAddress((void**)&wcf,  g_wcf);
    cudaGetSymbolAddress((void**)&dfcs, g_dfc_s);
    cudaGetSymbolAddress((void**)&dfcd, g_dfc_d);
    cudaGetSymbolAddress((void**)&dcfs, g_dcf_s);
    cudaGetSymbolAddress((void**)&dcfd, g_dcf_d);
    cudaGetSymbolAddress((void**)&W1t,  g_W1t);
    cudaGetSymbolAddress((void**)&W2t,  g_W2t);
    cudaGetSymbolAddress((void**)&H1,   g_H1);
    cudaGetSymbolAddress((void**)&c1h,  g_c1h);
    cudaGetSymbolAddress((void**)&H2,   g_H2);
    cudaGetSymbolAddress((void**)&psum, g_psum);
    cudaGetSymbolAddress((void**)&pcnt, g_pcnt);
    cudaGetSymbolAddress((void**)&cntc, g_cntc);
    cudaGetSymbolAddress((void**)&cntf, g_cntf);
    cudaGetSymbolAddress((void**)&bsum, g_bsum);
    cudaGetSymbolAddress((void**)&rpc,  g_rpc);
    cudaGetSymbolAddress((void**)&rpf,  g_rpf);
    cudaGetSymbolAddress((void**)&curc, g_curc);
    cudaGetSymbolAddress((void**)&curf, g_curf);
    cudaGetSymbolAddress((void**)&pfc,  g_pfc);
    cudaGetSymbolAddress((void**)&pcf,  g_pcf);

    // streams/events created once (host-side resources; device work identical per call)
    static cudaStream_t s2 = nullptr;
    static cudaEvent_t evFork = nullptr, evJoin = nullptr;
    if (!s2) {
        cudaStreamCreateWithFlags(&s2, cudaStreamNonBlocking);
        cudaEventCreateWithFlags(&evFork, cudaEventDisableTiming);
        cudaEventCreateWithFlags(&evJoin, cudaEventDisableTiming);
    }

    cudaMemsetAsync(dfcs, 0, NFACT * sizeof(float));
    cudaMemsetAsync(dfcd, 0, NCOMP * sizeof(float));
    cudaMemsetAsync(dcfs, 0, NCOMP * sizeof(float));
    cudaMemsetAsync(dcfd, 0, NFACT * sizeof(float));
    cudaMemsetAsync(cntc, 0, NCOMP * sizeof(int));
    cudaMemsetAsync(cntf, 0, NFACT * sizeof(int));
    cudaMemsetAsync(psum, 0, NB * sizeof(float));
    cudaMemsetAsync(pcnt, 0, NB * sizeof(float));

    const int nbC = (NCOMP + SCAN_BS - 1) / SCAN_BS;   // 40
    const int nbF = (NFACT + SCAN_BS - 1) / SCAN_BS;   // 391

    // fork: edge pipeline on s2, GEMM1 chain on stream 0 (concurrent)
    cudaEventRecord(evFork, 0);
    cudaStreamWaitEvent(s2, evFork, 0);

    // --- s2: gates + degrees + histograms -> scans -> scatter ---
    gate_deg2_kernel<<<(2 * NEDGE + 255) / 256, 256, 0, s2>>>(
        ea_fc, ea_cf, fc_src, fc_dst, cf_src, cf_dst, Wm, bm,
        wfc, wcf, dfcs, dfcd, dcfs, dcfd, cntc, cntf);
    scan_bsum2_kernel<<<nbC + nbF, SCAN_BS, 0, s2>>>(cntc, cntf, nbC, bsum);
    scan_tops2_kernel<<<2, 1024, 0, s2>>>(bsum, nbC, nbF, rpc, rpf);
    scan_write2_kernel<<<nbC + nbF, SCAN_BS, 0, s2>>>(cntc, cntf, bsum, nbC,
                                                      rpc, curc, rpf, curf);
    scatter2_kernel<<<(2 * NEDGE + 255) / 256, 256, 0, s2>>>(
        fc_src, fc_dst, wfc, dfcs, curc, pfc,
        cf_src, cf_dst, wcf, dcfs, curf, pcf);
    cudaEventRecord(evJoin, s2);

    // --- stream 0: weights prep + GEMM1 (overlaps with s2) ---
    prep_w_kernel<<<(DFACT * HID + HID * HID + 255) / 256, 256>>>(W1_fc, W2_cf, W1t, W2t);
    hgemm1_kernel<<<(NFACT + 127) / 128, 256>>>(x_fact, W1t, H1, NFACT, DFACT);

    // join: remaining chain needs both branches
    cudaStreamWaitEvent(0, evJoin, 0);

    // gather1 -> c1h = fp16(relu(agg + b1))
    gather_kernel<0><<<(NCOMP + 7) / 8, 256>>>(c1h, H1, pfc, rpc, dfcd,
                                               b1_fc, nullptr, nullptr,
                                               nullptr, nullptr, NCOMP);
    // GEMM2 (pure fp16)
    hgemm2_kernel<<<(NCOMP + 127) / 128, 256>>>(c1h, W2t, H2, NCOMP, HID);
    // gather2 + relu + classifier dot + pool (fused)
    gather_kernel<1><<<(NFACT + 7) / 8, 256>>>(nullptr, H2, pcf, rpf, dcfd,
                                               b2_cf, Wc, batch_fact,
                                               psum, pcnt, NFACT);
    final_kernel<<<1, NB>>>(psum, pcnt, bc, out);
}

// round 16
// speedup vs baseline: 1.4272x; 1.0454x over previous
#include <cuda_runtime.h>
#include <cuda_fp16.h>
#include <cstdint>

#define NFACT 100000
#define NCOMP 10000
#define NEDGE 800000
#define DFACT 768
#define HID   128
#define NB    256

#define PITCH 40                 // halves per smem row; 80B stride -> ldmatrix conflict-free
#define STGH  (128 * PITCH)      // halves per stage
#define SCAN_BS 256
#define FOFF 512                 // bsum offset for fact-relation blocks

// ---------------- scratch (device globals; no allocation allowed) ----------
__device__ float g_wfc[NEDGE];
__device__ float g_wcf[NEDGE];
__device__ float g_dfc_s[NFACT];
__device__ float g_dfc_d[NCOMP];
__device__ float g_dcf_s[NCOMP];
__device__ float g_dcf_d[NFACT];
__device__ __align__(16) __half g_W1t[(size_t)HID * DFACT];  // [n][k] fp16
__device__ __align__(16) __half g_W2t[(size_t)HID * HID];    // [n][k] fp16
__device__ __align__(16) __half g_H1[(size_t)NFACT * HID];
__device__ __align__(16) __half g_c1h[(size_t)NCOMP * HID];  // relu(agg+b1) fp16
__device__ __align__(16) __half g_H2[(size_t)NCOMP * HID];
__device__ float g_psum[NB];
__device__ float g_pcnt[NB];
// CSR scratch
__device__ int   g_cntc[NCOMP];
__device__ int   g_cntf[NFACT];
__device__ int   g_bsum[1024];
__device__ int   g_rpc[NCOMP + 1];
__device__ int   g_rpf[NFACT + 1];
__device__ int   g_curc[NCOMP];
__device__ int   g_curf[NFACT];
__device__ uint2 g_pfc[NEDGE];
__device__ uint2 g_pcf[NEDGE];

// ---------------- helpers --------------------------------------------------
__device__ __forceinline__ void mma_f16(float* c, const uint32_t* a, const uint32_t* b) {
    asm volatile(
        "mma.sync.aligned.m16n8k16.row.col.f32.f16.f16.f32 "
        "{%0,%1,%2,%3}, {%4,%5,%6,%7}, {%8,%9}, {%0,%1,%2,%3};"
        : "+f"(c[0]), "+f"(c[1]), "+f"(c[2]), "+f"(c[3])
        : "r"(a[0]), "r"(a[1]), "r"(a[2]), "r"(a[3]), "r"(b[0]), "r"(b[1]));
}
__device__ __forceinline__ void ldsm_x4(uint32_t& r0, uint32_t& r1, uint32_t& r2,
                                        uint32_t& r3, const __half* p) {
    uint32_t a = (uint32_t)__cvta_generic_to_shared(p);
    asm volatile("ldmatrix.sync.aligned.m8n8.x4.shared.b16 {%0,%1,%2,%3}, [%4];"
                 : "=r"(r0), "=r"(r1), "=r"(r2), "=r"(r3) : "r"(a));
}
#define CP_COMMIT() asm volatile("cp.async.commit_group;")
#define CP_WAIT1()  asm volatile("cp.async.wait_group 1;")
__device__ __forceinline__ void cpa16(__half* sp, const __half* gp) {
    uint32_t sa = (uint32_t)__cvta_generic_to_shared(sp);
    asm volatile("cp.async.cg.shared.global [%0], [%1], 16;" :: "r"(sa), "l"(gp));
}
__device__ __forceinline__ float inv_sqrt_deg(float d) {
    return (d > 0.f) ? rsqrtf(d) : 0.f;
}

// ---------------- fused edge kernels ---------------------------------------
__global__ void gate_deg2_kernel(const float* __restrict__ eaA, const float* __restrict__ eaB,
                                 const int* __restrict__ srcA, const int* __restrict__ dstA,
                                 const int* __restrict__ srcB, const int* __restrict__ dstB,
                                 const float* __restrict__ Wm, const float* __restrict__ bm,
                                 float* __restrict__ wA, float* __restrict__ wB,
                                 float* __restrict__ degsA, float* __restrict__ degdA,
                                 float* __restrict__ degsB, float* __restrict__ degdB,
                                 int* __restrict__ cntA, int* __restrict__ cntB) {
    int i = blockIdx.x * blockDim.x + threadIdx.x;
    int e = (i < NEDGE) ? i : i - NEDGE;
    if (i >= 2 * NEDGE) return;
    const float* ea = (i < NEDGE) ? eaA : eaB;
    float a0 = ea[2 * e + 0], a1 = ea[2 * e + 1];
    float z  = a0 * Wm[0] + a1 * Wm[1] + bm[0];
    float ww = 1.f / (1.f + expf(-z));
    if (i < NEDGE) {
        wA[e] = ww;
        int d = dstA[e];
        atomicAdd(&degsA[srcA[e]], ww);
        atomicAdd(&degdA[d], ww);
        atomicAdd(&cntA[d], 1);
    } else {
        wB[e] = ww;
        int d = dstB[e];
        atomicAdd(&degsB[srcB[e]], ww);
        atomicAdd(&degdB[d], ww);
        atomicAdd(&cntB[d], 1);
    }
}

__global__ void prep_w_kernel(const float* __restrict__ W1, const float* __restrict__ W2,
                              __half* __restrict__ W1t, __half* __restrict__ W2t) {
    int i = blockIdx.x * blockDim.x + threadIdx.x;
    int n1 = DFACT * HID;
    if (i < n1) {
        int k = i >> 7, n = i & 127;
        W1t[(size_t)n * DFACT + k] = __float2half_rn(W1[i]);
    } else if (i < n1 + HID * HID) {
        int j = i - n1;
        int k = j >> 7, n = j & 127;
        W2t[(size_t)n * HID + k] = __float2half_rn(W2[j]);
    }
}

// ---------------- CSR build (per-relation) ----------------------------------
__global__ void scan_bsum_kernel(const int* __restrict__ cnt, int n, int* __restrict__ bsum) {
    __shared__ int sh[SCAN_BS];
    int i = blockIdx.x * SCAN_BS + threadIdx.x;
    sh[threadIdx.x] = (i < n) ? cnt[i] : 0;
    __syncthreads();
    for (int o = SCAN_BS / 2; o; o >>= 1) {
        if (threadIdx.x < o) sh[threadIdx.x] += sh[threadIdx.x + o];
        __syncthreads();
    }
    if (threadIdx.x == 0) bsum[blockIdx.x] = sh[0];
}

__global__ void scan_tops_kernel(int* __restrict__ bsum, int nb,
                                 int* __restrict__ rowptr, int n) {
    __shared__ int sh[1024];
    int tid = threadIdx.x;
    int v = (tid < nb) ? bsum[tid] : 0;
    sh[tid] = v;
    __syncthreads();
    for (int o = 1; o < 1024; o <<= 1) {
        int t = (tid >= o) ? sh[tid - o] : 0;
        __syncthreads();
        sh[tid] += t;
        __syncthreads();
    }
    if (tid < nb) bsum[tid] = sh[tid] - v;
    if (tid == 0) rowptr[n] = sh[1023];
}

__global__ void scan_write_kernel(const int* __restrict__ cnt, const int* __restrict__ bsum,
                                  int n, int* __restrict__ rowptr, int* __restrict__ cur) {
    __shared__ int sh[SCAN_BS];
    int tid = threadIdx.x;
    int i = blockIdx.x * SCAN_BS + tid;
    int v = (i < n) ? cnt[i] : 0;
    sh[tid] = v;
    __syncthreads();
    for (int o = 1; o < SCAN_BS; o <<= 1) {
        int t = (tid >= o) ? sh[tid - o] : 0;
        __syncthreads();
        sh[tid] += t;
        __syncthreads();
    }
    if (i < n) {
        int ex = sh[tid] - v + bsum[blockIdx.x];
        rowptr[i] = ex;
        cur[i] = ex;
    }
}

__global__ void scatter_kernel(const int* __restrict__ src, const int* __restrict__ dst,
                               const float* __restrict__ w, const float* __restrict__ degs,
                               int* __restrict__ cur, uint2* __restrict__ pk, int E) {
    int e = blockIdx.x * blockDim.x + threadIdx.x;
    if (e >= E) return;
    int d = dst[e], s = src[e];
    int pos = atomicAdd(&cur[d], 1);
    pk[pos] = make_uint2((uint32_t)s,
                         __float_as_uint(w[e] * inv_sqrt_deg(degs[s])));
}

// ---------------- gather (warp per node, x4 unrolled) -----------------------
template <int MODE>
__global__ void gather_kernel(__half* __restrict__ outh, const __half* __restrict__ h,
                              const uint2* __restrict__ packed,
                              const int* __restrict__ rowptr,
                              const float* __restrict__ deg_d,
                              const float* __restrict__ bias,
                              const float* __restrict__ Wc,
                              const int* __restrict__ batch,
                              float* __restrict__ psum, float* __restrict__ pcnt,
                              int n) {
    int node = blockIdx.x * (blockDim.x >> 5) + (threadIdx.x >> 5);
    if (node >= n) return;
    int lane = threadIdx.x & 31;
    int r0 = __ldg(rowptr + node), r1 = __ldg(rowptr + node + 1);
    float4 acc = make_float4(0.f, 0.f, 0.f, 0.f);
    for (int base = r0; base < r1; base += 32) {
        int nit = min(32, r1 - base);
        uint2 meta = (lane < nit) ? __ldg(packed + base + lane) : make_uint2(0u, 0u);
        int nit4 = (nit + 3) & ~3;
        for (int j = 0; j < nit4; j += 4) {
            int   s0 = __shfl_sync(0xffffffffu, (int)meta.x, j + 0);
            int   s1 = __shfl_sync(0xffffffffu, (int)meta.x, (j + 1) & 31);
            int   s2 = __shfl_sync(0xffffffffu, (int)meta.x, (j + 2) & 31);
            int   s3 = __shfl_sync(0xffffffffu, (int)meta.x, (j + 3) & 31);
            float w0 = __uint_as_float(__shfl_sync(0xffffffffu, meta.y, j + 0));
            float w1 = __uint_as_float(__shfl_sync(0xffffffffu, meta.y, (j + 1) & 31));
            float w2 = __uint_as_float(__shfl_sync(0xffffffffu, meta.y, (j + 2) & 31));
            float w3 = __uint_as_float(__shfl_sync(0xffffffffu, meta.y, (j + 3) & 31));
            uint2 v0 = *reinterpret_cast<const uint2*>(h + (size_t)s0 * 128 + lane * 4);
            uint2 v1 = *reinterpret_cast<const uint2*>(h + (size_t)s1 * 128 + lane * 4);
            uint2 v2 = *reinterpret_cast<const uint2*>(h + (size_t)s2 * 128 + lane * 4);
            uint2 v3 = *reinterpret_cast<const uint2*>(h + (size_t)s3 * 128 + lane * 4);
#define ACC(V, W)                                                              \
            {                                                                  \
                float2 fa = __half22float2(*reinterpret_cast<__half2*>(&V.x)); \
                float2 fb = __half22float2(*reinterpret_cast<__half2*>(&V.y)); \
                acc.x += (W) * fa.x; acc.y += (W) * fa.y;                      \
                acc.z += (W) * fb.x; acc.w += (W) * fb.y;                      \
            }
            ACC(v0, w0) ACC(v1, w1) ACC(v2, w2) ACC(v3, w3)
#undef ACC
        }
    }
    float dd = inv_sqrt_deg(__ldg(deg_d + node));
    acc.x *= dd; acc.y *= dd; acc.z *= dd; acc.w *= dd;
    float4 bb = reinterpret_cast<const float4*>(bias)[lane];
    acc.x = fmaxf(acc.x + bb.x, 0.f);
    acc.y = fmaxf(acc.y + bb.y, 0.f);
    acc.z = fmaxf(acc.z + bb.z, 0.f);
    acc.w = fmaxf(acc.w + bb.w, 0.f);
    if (MODE == 0) {
        __half2 o0 = __floats2half2_rn(acc.x, acc.y);
        __half2 o1 = __floats2half2_rn(acc.z, acc.w);
        *reinterpret_cast<uint2*>(outh + (size_t)node * 128 + lane * 4) =
            make_uint2(*reinterpret_cast<uint32_t*>(&o0), *reinterpret_cast<uint32_t*>(&o1));
    } else {
        float4 wc = reinterpret_cast<const float4*>(Wc)[lane];
        float s = acc.x * wc.x + acc.y * wc.y + acc.z * wc.z + acc.w * wc.w;
#pragma unroll
        for (int o = 16; o; o >>= 1) s += __shfl_down_sync(0xffffffffu, s, o);
        if (lane == 0) {
            int g = batch[node];
            atomicAdd(&psum[g], s);
            atomicAdd(&pcnt[g], 1.f);
        }
    }
}

// ---------------- shared MMA compute (ldmatrix fragments) -------------------
#define MMA_TILE_COMPUTE(as, bs)                                               \
    do {                                                                       \
        _Pragma("unroll")                                                      \
        for (int kk = 0; kk < 32; kk += 16) {                                  \
            uint32_t afr[2][4], bfr[8][2];                                     \
            _Pragma("unroll")                                                  \
            for (int mi = 0; mi < 2; mi++)                                     \
                ldsm_x4(afr[mi][0], afr[mi][1], afr[mi][2], afr[mi][3],        \
                        &(as)[(wm + mi * 16 + lrow) * PITCH + kk + lcol]);     \
            _Pragma("unroll")                                                  \
            for (int nb = 0; nb < 4; nb++) {                                   \
                uint32_t q0, q1, q2, q3;                                       \
                ldsm_x4(q0, q1, q2, q3,                                        \
                        &(bs)[(wn + nb * 16 + lrow) * PITCH + kk + lcol]);     \
                bfr[2 * nb][0] = q0; bfr[2 * nb + 1][0] = q1;                  \
                bfr[2 * nb][1] = q2; bfr[2 * nb + 1][1] = q3;                  \
            }                                                                  \
            _Pragma("unroll")                                                  \
            for (int mi = 0; mi < 2; mi++)                                     \
                _Pragma("unroll")                                              \
                for (int ni = 0; ni < 8; ni++)                                 \
                    mma_f16(acc[mi][ni], afr[mi], bfr[ni]);                    \
        }                                                                      \
    } while (0)

#define MMA_EPILOGUE(C, M)                                                     \
    do {                                                                       \
        _Pragma("unroll")                                                      \
        for (int mi = 0; mi < 2; mi++)                                         \
            _Pragma("unroll")                                                  \
            for (int ni = 0; ni < 8; ni++) {                                   \
                int r1 = row0 + wm + mi * 16 + gid;                            \
                int r2 = r1 + 8;                                               \
                int c  = wn + ni * 8 + tid4 * 2;                               \
                if (r1 < (M))                                                  \
                    *reinterpret_cast<__half2*>((C) + (size_t)r1 * 128 + c) =  \
                        __floats2half2_rn(acc[mi][ni][0], acc[mi][ni][1]);     \
                if (r2 < (M))                                                  \
                    *reinterpret_cast<__half2*>((C) + (size_t)r2 * 128 + c) =  \
                        __floats2half2_rn(acc[mi][ni][2], acc[mi][ni][3]);     \
            }                                                                  \
    } while (0)

// ---------------- GEMM1: A f32 -> cvt in reg -> STS; B fp16 cp.async --------
__global__ __launch_bounds__(256) void hgemm1_kernel(
        const float* __restrict__ A, const __half* __restrict__ Bt,
        __half* __restrict__ C, int M, int K) {
    __shared__ __half Asm[2][STGH];
    __shared__ __half Bsm[2][STGH];

    const int tid  = threadIdx.x;
    const int wid  = tid >> 5;
    const int lane = tid & 31;
    const int gid  = lane >> 2;
    const int tid4 = lane & 3;
    const int wm   = (wid & 3) * 32;
    const int wn   = (wid >> 2) * 64;
    const int row0 = blockIdx.x * 128;
    const int nt   = K >> 5;
    const int lrow = ((lane >> 3) & 1) * 8 + (lane & 7);   // ldmatrix row offset
    const int lcol = (lane >> 4) * 8;                      // ldmatrix col offset

    float acc[2][8][4] = {};
    int aR[4]; const int aC = (tid & 7) * 4;
    int bR[2]; const int bK = (tid & 3) * 8;
#pragma unroll
    for (int i = 0; i < 4; i++) aR[i] = (tid + i * 256) >> 3;
#pragma unroll
    for (int i = 0; i < 2; i++) bR[i] = (tid + i * 256) >> 2;

    float4 av[4];
#define G_LDG(t)                                                               \
    do {                                                                       \
        int k0 = (t) * 32;                                                     \
        _Pragma("unroll")                                                      \
        for (int i = 0; i < 4; i++) {                                          \
            int r = row0 + aR[i];                                              \
            av[i] = (r < M) ? *reinterpret_cast<const float4*>(                \
                                  A + (size_t)r * K + k0 + aC)                 \
                            : make_float4(0.f, 0.f, 0.f, 0.f);                 \
        }                                                                      \
    } while (0)
#define G_CPB(t)                                                               \
    do {                                                                       \
        int k0 = (t) * 32;                                                     \
        _Pragma("unroll")                                                      \
        for (int i = 0; i < 2; i++)                                            \
            cpa16(&Bsm[(t) & 1][bR[i] * PITCH + bK],                           \
                  Bt + (size_t)bR[i] * K + k0 + bK);                           \
    } while (0)
#define G_STS(t)                                                               \
    do {                                                                       \
        _Pragma("unroll")                                                      \
        for (int i = 0; i < 4; i++) {                                          \
            __half2 h0 = __floats2half2_rn(av[i].x, av[i].y);                  \
            __half2 h1 = __floats2half2_rn(av[i].z, av[i].w);                  \
            *reinterpret_cast<uint2*>(&Asm[(t) & 1][aR[i] * PITCH + aC]) =     \
                make_uint2(*reinterpret_cast<uint32_t*>(&h0),                  \
                           *reinterpret_cast<uint32_t*>(&h1));                 \
        }                                                                      \
    } while (0)

    G_LDG(0);
    G_CPB(0); CP_COMMIT();

    for (int t = 0; t < nt; t++) {
        G_STS(t);
        if (t + 1 < nt) { G_LDG(t + 1); G_CPB(t + 1); }
        CP_COMMIT();
        CP_WAIT1();
        __syncthreads();
        MMA_TILE_COMPUTE(Asm[t & 1], Bsm[t & 1]);
        __syncthreads();
    }

    MMA_EPILOGUE(C, M);
#undef G_LDG
#undef G_CPB
#undef G_STS
}

// ---------------- GEMM2: both operands fp16 via cp.async --------------------
__global__ __launch_bounds__(256) void hgemm2_kernel(
        const __half* __restrict__ A, const __half* __restrict__ Bt,
        __half* __restrict__ C, int M, int K) {
    __shared__ __half Asm[2][STGH];
    __shared__ __half Bsm[2][STGH];

    const int tid  = threadIdx.x;
    const int wid  = tid >> 5;
    const int lane = tid & 31;
    const int gid  = lane >> 2;
    const int tid4 = lane & 3;
    const int wm   = (wid & 3) * 32;
    const int wn   = (wid >> 2) * 64;
    const int row0 = blockIdx.x * 128;
    const int nt   = K >> 5;
    const int lrow = ((lane >> 3) & 1) * 8 + (lane & 7);
    const int lcol = (lane >> 4) * 8;

    float acc[2][8][4] = {};
    int xR[2]; const int xK = (tid & 3) * 8;
#pragma unroll
    for (int i = 0; i < 2; i++) xR[i] = (tid + i * 256) >> 2;

#define G2_CP(t)                                                               \
    do {                                                                       \
        int k0 = (t) * 32;                                                     \
        _Pragma("unroll")                                                      \
        for (int i = 0; i < 2; i++) {                                          \
            int r = row0 + xR[i];                                              \
            const __half* gp = (r < M) ? A + (size_t)r * K + k0 + xK           \
                                       : A + k0 + xK;                          \
            cpa16(&Asm[(t) & 1][xR[i] * PITCH + xK], gp);                      \
            cpa16(&Bsm[(t) & 1][xR[i] * PITCH + xK],                           \
                  Bt + (size_t)xR[i] * K + k0 + xK);                           \
        }                                                                      \
    } while (0)

    G2_CP(0); CP_COMMIT();

    for (int t = 0; t < nt; t++) {
        if (t + 1 < nt) G2_CP(t + 1);
        CP_COMMIT();
        CP_WAIT1();
        __syncthreads();
        MMA_TILE_COMPUTE(Asm[t & 1], Bsm[t & 1]);
        __syncthreads();
    }

    MMA_EPILOGUE(C, M);
#undef G2_CP
}

__global__ void final_kernel(const float* __restrict__ psum,
                             const float* __restrict__ pcnt,
                             const float* __restrict__ bc,
                             float* __restrict__ out) {
    int g = threadIdx.x;
    if (g < NB) out[g] = psum[g] / fmaxf(pcnt[g], 1.f) + bc[0];
}

// ---------------- launch ---------------------------------------------------
extern "C" void kernel_launch(void* const* d_in, const int* in_sizes, int n_in,
                              void* d_out, int out_size) {
    const float* x_fact     = (const float*)d_in[0];
    const float* ea_fc      = (const float*)d_in[2];
    const float* ea_cf      = (const float*)d_in[3];
    const int*   fc_src     = (const int*)d_in[4];
    const int*   fc_dst     = (const int*)d_in[5];
    const int*   cf_src     = (const int*)d_in[6];
    const int*   cf_dst     = (const int*)d_in[7];
    const int*   batch_fact = (const int*)d_in[8];
    const float* Wm         = (const float*)d_in[9];
    const float* bm         = (const float*)d_in[10];
    const float* W1_fc      = (const float*)d_in[11];
    const float* b1_fc      = (const float*)d_in[12];
    const float* W2_cf      = (const float*)d_in[17];
    const float* b2_cf      = (const float*)d_in[18];
    const float* Wc         = (const float*)d_in[19];
    const float* bc         = (const float*)d_in[20];
    float* out = (float*)d_out;

    float *wfc, *wcf, *dfcs, *dfcd, *dcfs, *dcfd, *psum, *pcnt;
    __half *W1t, *W2t, *H1, *c1h, *H2;
    int *cntc, *cntf, *bsum, *rpc, *rpf, *curc, *curf;
    uint2 *pfc, *pcf;
    cudaGetSymbolAddress((void**)&wfc,  g_wfc);
    cudaGetSymbolAddress((void**)&wcf,  g_wcf);
    cudaGetSymbolAddress((void**)&dfcs, g_dfc_s);
    cudaGetSymbolAddress((void**)&dfcd, g_dfc_d);
    cudaGetSymbolAddress((void**)&dcfs, g_dcf_s);
    cudaGetSymbolAddress((void**)&dcfd, g_dcf_d);
    cudaGetSymbolAddress((void**)&W1t,  g_W1t);
    cudaGetSymbolAddress((void**)&W2t,  g_W2t);
    cudaGetSymbolAddress((void**)&H1,   g_H1);
    cudaGetSymbolAddress((void**)&c1h,  g_c1h);
    cudaGetSymbolAddress((void**)&H2,   g_H2);
    cudaGetSymbolAddress((void**)&psum, g_psum);
    cudaGetSymbolAddress((void**)&pcnt, g_pcnt);
    cudaGetSymbolAddress((void**)&cntc, g_cntc);
    cudaGetSymbolAddress((void**)&cntf, g_cntf);
    cudaGetSymbolAddress((void**)&bsum, g_bsum);
    cudaGetSymbolAddress((void**)&rpc,  g_rpc);
    cudaGetSymbolAddress((void**)&rpf,  g_rpf);
    cudaGetSymbolAddress((void**)&curc, g_curc);
    cudaGetSymbolAddress((void**)&curf, g_curf);
    cudaGetSymbolAddress((void**)&pfc,  g_pfc);
    cudaGetSymbolAddress((void**)&pcf,  g_pcf);

    // streams/events created once (host-side resources; device work identical per call)
    static cudaStream_t s2 = nullptr, s3 = nullptr;
    static cudaEvent_t evFork = nullptr, evGate = nullptr, evFC = nullptr, evCF = nullptr;
    if (!s2) {
        cudaStreamCreateWithFlags(&s2, cudaStreamNonBlocking);
        cudaStreamCreateWithFlags(&s3, cudaStreamNonBlocking);
        cudaEventCreateWithFlags(&evFork, cudaEventDisableTiming);
        cudaEventCreateWithFlags(&evGate, cudaEventDisableTiming);
        cudaEventCreateWithFlags(&evFC,   cudaEventDisableTiming);
        cudaEventCreateWithFlags(&evCF,   cudaEventDisableTiming);
    }

    const int nbC = (NCOMP + SCAN_BS - 1) / SCAN_BS;   // 40
    const int nbF = (NFACT + SCAN_BS - 1) / SCAN_BS;   // 391

    // fork s2/s3 from stream0 head
    cudaEventRecord(evFork, 0);
    cudaStreamWaitEvent(s2, evFork, 0);

    // --- s2: memsets + gates/degrees/histograms (both relations) ---
    cudaMemsetAsync(dfcs, 0, NFACT * sizeof(float), s2);
    cudaMemsetAsync(dfcd, 0, NCOMP * sizeof(float), s2);
    cudaMemsetAsync(dcfs, 0, NCOMP * sizeof(float), s2);
    cudaMemsetAsync(dcfd, 0, NFACT * sizeof(float), s2);
    cudaMemsetAsync(cntc, 0, NCOMP * sizeof(int), s2);
    cudaMemsetAsync(cntf, 0, NFACT * sizeof(int), s2);
    cudaMemsetAsync(psum, 0, NB * sizeof(float), s2);
    cudaMemsetAsync(pcnt, 0, NB * sizeof(float), s2);
    // submission #1
    gate_deg2_kernel<<<(2 * NEDGE + 255) / 256, 256, 0, s2>>>(
        ea_fc, ea_cf, fc_src, fc_dst, cf_src, cf_dst, Wm, bm,
        wfc, wcf, dfcs, dfcd, dcfs, dcfd, cntc, cntf);
    cudaEventRecord(evGate, s2);
    cudaStreamWaitEvent(s3, evGate, 0);

    // submission #2: weights prep on stream0
    prep_w_kernel<<<(DFACT * HID + HID * HID + 255) / 256, 256>>>(W1_fc, W2_cf, W1t, W2t);
    // submission #3: fc-relation block sums
    scan_bsum_kernel<<<nbC, SCAN_BS, 0, s2>>>(cntc, NCOMP, bsum);
    // submission #4: GEMM1 (profiled slot — measures overlap interference)
    hgemm1_kernel<<<(NFACT + 127) / 128, 256>>>(x_fact, W1t, H1, NFACT, DFACT);

    // --- s2: finish fc CSR + scatter ---
    scan_tops_kernel<<<1, 1024, 0, s2>>>(bsum, nbC, rpc, NCOMP);
    scan_write_kernel<<<nbC, SCAN_BS, 0, s2>>>(cntc, bsum, NCOMP, rpc, curc);
    scatter_kernel<<<(NEDGE + 255) / 256, 256, 0, s2>>>(fc_src, fc_dst, wfc, dfcs,
                                                        curc, pfc, NEDGE);
    cudaEventRecord(evFC, s2);

    // --- s3: cf CSR + scatter (overlaps GEMM1 / gather1 / GEMM2) ---
    scan_bsum_kernel<<<nbF, SCAN_BS, 0, s3>>>(cntf, NFACT, bsum + FOFF);
    scan_tops_kernel<<<1, 1024, 0, s3>>>(bsum + FOFF, nbF, rpf, NFACT);
    scan_write_kernel<<<nbF, SCAN_BS, 0, s3>>>(cntf, bsum + FOFF, NFACT, rpf, curf);
    scatter_kernel<<<(NEDGE + 255) / 256, 256, 0, s3>>>(cf_src, cf_dst, wcf, dcfs,
                                                        curf, pcf, NEDGE);
    cudaEventRecord(evCF, s3);

    // --- stream0 tail ---
    cudaStreamWaitEvent(0, evFC, 0);
    gather_kernel<0><<<(NCOMP + 7) / 8, 256>>>(c1h, H1, pfc, rpc, dfcd,
                                               b1_fc, nullptr, nullptr,
                                               nullptr, nullptr, NCOMP);
    hgemm2_kernel<<<(NCOMP + 127) / 128, 256>>>(c1h, W2t, H2, NCOMP, HID);
    cudaStreamWaitEvent(0, evCF, 0);
    gather_kernel<1><<<(NFACT + 7) / 8, 256>>>(nullptr, H2, pcf, rpf, dcfd,
                                               b2_cf, Wc, batch_fact,
                                               psum, pcnt, NFACT);
    final_kernel<<<1, NB>>>(psum, pcnt, bc, out);
}